// round 2
// baseline (speedup 1.0000x reference)
#include <cuda_runtime.h>
#include <cstdint>
#include <cstddef>
#include <math.h>

// Problem constants
#define B_   2
#define T_   4
#define NQ_  576
#define NK_  576
#define D_   1024
#define H_   16
#define DH_  64
#define TOK  (B_*T_*NQ_)          // 4608 tokens (q and kv counts equal)
#define NEGBIG (-1.7014118e38f)   // float32 min / 2

// Scratch (device globals; no dynamic allocation allowed)
__device__ float g_Q[TOK * D_];
__device__ float g_K[TOK * D_];
__device__ float g_V[TOK * D_];
__device__ float g_Y[TOK * D_];
__device__ float g_qm[TOK];
__device__ float g_km[TOK];
__device__ int   g_mask_mode[2];   // 0 = uint8, 1 = int32, 2 = float32

// ---------------------------------------------------------------------------
// Mask dtype detection: inspect first 1152 32-bit words (4608 bytes — safe for
// every candidate dtype). Random uint8 bools -> words with bytes in {0,1},
// generally >1. int32 bools -> words in {0,1}. float bools -> {0, 0x3f800000}.
// ---------------------------------------------------------------------------
__global__ void detect_mask_kernel(const unsigned* __restrict__ qm,
                                   const unsigned* __restrict__ km, int nints)
{
    __shared__ int s_i, s_f;
    for (int b = 0; b < 2; b++) {
        if (threadIdx.x == 0) { s_i = 1; s_f = 1; }
        __syncthreads();
        const unsigned* p = b ? km : qm;
        int li = 1, lf = 1;
        for (int i = threadIdx.x; i < nints; i += blockDim.x) {
            unsigned v = p[i];
            if (v > 1u) li = 0;
            if (v != 0u && v != 0x3f800000u) lf = 0;
        }
        if (!li) atomicAnd(&s_i, 0);
        if (!lf) atomicAnd(&s_f, 0);
        __syncthreads();
        if (threadIdx.x == 0)
            g_mask_mode[b] = s_i ? 1 : (s_f ? 2 : 0);
        __syncthreads();
    }
}

__global__ void expand_mask_kernel(const void* __restrict__ src,
                                   float* __restrict__ dst, int n, int which)
{
    int mode = g_mask_mode[which];
    int i = blockIdx.x * blockDim.x + threadIdx.x;
    if (i >= n) return;
    bool m;
    if (mode == 1)      m = ((const int*)src)[i] != 0;
    else if (mode == 2) m = ((const float*)src)[i] != 0.f;
    else                m = ((const unsigned char*)src)[i] != 0;
    dst[i] = m ? 1.f : 0.f;
}

// ---------------------------------------------------------------------------
// GEMM: C[M,N] = A[M,K] @ W[N,K]^T + bias[N]   (torch Linear semantics)
// 128x128 block, BK=16, 256 threads, 8x8 microtile, register prefetch.
// ---------------------------------------------------------------------------
__global__ void __launch_bounds__(256)
gemm_nt_bias(const float* __restrict__ A, const float* __restrict__ W,
             const float* __restrict__ bias, float* __restrict__ C,
             int M, int N, int K)
{
    __shared__ float As[16][132];
    __shared__ float Ws[16][132];

    const int tid = threadIdx.x;
    const int tx = tid & 15;      // 16 col groups (8 cols each)
    const int ty = tid >> 4;      // 16 row groups (8 rows each)
    const int m0 = blockIdx.y * 128;
    const int n0 = blockIdx.x * 128;

    const int lr = tid >> 2;      // 0..63 (row within half-tile)
    const int lq = tid & 3;       // quad (4 floats) within 16-wide k row

    const float* Abase = A + (size_t)(m0 + lr) * K + lq * 4;
    const float* Wbase = W + (size_t)(n0 + lr) * K + lq * 4;

    float acc[8][8];
    #pragma unroll
    for (int i = 0; i < 8; i++)
        #pragma unroll
        for (int j = 0; j < 8; j++) acc[i][j] = 0.f;

    float4 a0 = *(const float4*)(Abase);
    float4 a1 = *(const float4*)(Abase + (size_t)64 * K);
    float4 w0 = *(const float4*)(Wbase);
    float4 w1 = *(const float4*)(Wbase + (size_t)64 * K);

    const int ntiles = K >> 4;
    for (int kt = 0; kt < ntiles; kt++) {
        As[lq*4+0][lr]    = a0.x; As[lq*4+1][lr]    = a0.y;
        As[lq*4+2][lr]    = a0.z; As[lq*4+3][lr]    = a0.w;
        As[lq*4+0][lr+64] = a1.x; As[lq*4+1][lr+64] = a1.y;
        As[lq*4+2][lr+64] = a1.z; As[lq*4+3][lr+64] = a1.w;
        Ws[lq*4+0][lr]    = w0.x; Ws[lq*4+1][lr]    = w0.y;
        Ws[lq*4+2][lr]    = w0.z; Ws[lq*4+3][lr]    = w0.w;
        Ws[lq*4+0][lr+64] = w1.x; Ws[lq*4+1][lr+64] = w1.y;
        Ws[lq*4+2][lr+64] = w1.z; Ws[lq*4+3][lr+64] = w1.w;
        __syncthreads();

        if (kt + 1 < ntiles) {
            const float* Ap2 = Abase + (kt + 1) * 16;
            const float* Wp2 = Wbase + (kt + 1) * 16;
            a0 = *(const float4*)(Ap2);
            a1 = *(const float4*)(Ap2 + (size_t)64 * K);
            w0 = *(const float4*)(Wp2);
            w1 = *(const float4*)(Wp2 + (size_t)64 * K);
        }

        #pragma unroll
        for (int kk = 0; kk < 16; kk++) {
            float av[8], wv[8];
            *(float4*)&av[0] = *(const float4*)&As[kk][ty * 8];
            *(float4*)&av[4] = *(const float4*)&As[kk][ty * 8 + 4];
            *(float4*)&wv[0] = *(const float4*)&Ws[kk][tx * 8];
            *(float4*)&wv[4] = *(const float4*)&Ws[kk][tx * 8 + 4];
            #pragma unroll
            for (int i = 0; i < 8; i++)
                #pragma unroll
                for (int j = 0; j < 8; j++)
                    acc[i][j] = fmaf(av[i], wv[j], acc[i][j]);
        }
        __syncthreads();
    }

    float bv[8];
    #pragma unroll
    for (int j = 0; j < 8; j++) bv[j] = bias[n0 + tx * 8 + j];

    #pragma unroll
    for (int i = 0; i < 8; i++) {
        float* cp = C + (size_t)(m0 + ty * 8 + i) * N + n0 + tx * 8;
        float4 r0, r1;
        r0.x = acc[i][0] + bv[0]; r0.y = acc[i][1] + bv[1];
        r0.z = acc[i][2] + bv[2]; r0.w = acc[i][3] + bv[3];
        r1.x = acc[i][4] + bv[4]; r1.y = acc[i][5] + bv[5];
        r1.z = acc[i][6] + bv[6]; r1.w = acc[i][7] + bv[7];
        *(float4*)cp       = r0;
        *(float4*)(cp + 4) = r1;
    }
}

// ---------------------------------------------------------------------------
// 4D RoPE: X[tok, h*64 + 2j(+1)] rotated by (cos,sin) of
// arg_j = 0.5*pi * coord[axis(j)] * freq[axis(j)][j'] ; pairs repeated per head.
// One block per token.
// ---------------------------------------------------------------------------
__global__ void rope_kernel(float* __restrict__ X, const float* __restrict__ coords,
                            const float* __restrict__ f0, const float* __restrict__ f1,
                            const float* __restrict__ f2)
{
    __shared__ float cs[32], sn[32];
    const int tok = blockIdx.x;
    const int tid = threadIdx.x;

    if (tid < 32) {
        float coord, fr;
        if (tid < 12)      { coord = coords[tok * 3 + 0]; fr = f0[tid]; }
        else if (tid < 22) { coord = coords[tok * 3 + 1]; fr = f1[tid - 12]; }
        else               { coord = coords[tok * 3 + 2]; fr = f2[tid - 22]; }
        float arg = 1.5707963267948966f * coord * fr;
        float s, c;
        sincosf(arg, &s, &c);
        sn[tid] = s; cs[tid] = c;
    }
    __syncthreads();

    float* xp = X + (size_t)tok * D_;
    for (int p = tid; p < H_ * 32; p += blockDim.x) {
        int h = p >> 5, j = p & 31;
        int idx = h * 64 + j * 2;
        float x0 = xp[idx], x1 = xp[idx + 1];
        float c = cs[j], s = sn[j];
        xp[idx]     = x0 * c - x1 * s;
        xp[idx + 1] = x1 * c + x0 * s;
    }
}

// ---------------------------------------------------------------------------
// Flash-style attention per (frame = b*T+t, head) with fused distance bias.
// 64-query block per CTA, 9 k-tiles of 64. 256 threads, 4x4 microtiles.
// ---------------------------------------------------------------------------
#define SSTR 68   // smem row stride (floats), mult of 4 for float4, +4 pad

__global__ void __launch_bounds__(256)
attn_kernel(const float* __restrict__ Q, const float* __restrict__ K,
            const float* __restrict__ V,
            const float* __restrict__ cq, const float* __restrict__ ck,
            const float* __restrict__ qm, const float* __restrict__ km,
            const float* __restrict__ alpha, float* __restrict__ Y)
{
    extern __shared__ float smem[];
    float* Qs  = smem;                 // [64 d][64 r] transposed, stride SSTR
    float* KVs = smem + 64 * SSTR;     // K phase: [d][c]; V phase: [c][d]
    float* Ps  = smem + 2 * 64 * SSTR; // [c][r]
    float* qy  = smem + 3 * 64 * SSTR;
    float* qx  = qy + 64;
    float* kyv = qx + 64;
    float* kxv = kyv + 64;
    float* qpd = kxv + 64;
    float* kpd = qpd + 64;

    const int tid = threadIdx.x;
    const int tx = tid & 15, ty = tid >> 4;
    const int qb = blockIdx.x;            // 0..8
    const int h  = blockIdx.y & 15;
    const int bt = blockIdx.y >> 4;       // 0..7
    const int tok0 = bt * NQ_;
    const float alph = alpha[h];
    const int q0 = qb * 64;

    // Load Q block (transposed) + q coords/masks
    for (int idx = tid; idx < 4096; idx += 256) {
        int r = idx >> 6, d = idx & 63;
        Qs[d * SSTR + r] = Q[(size_t)(tok0 + q0 + r) * D_ + h * 64 + d];
    }
    if (tid < 64) {
        int t = tok0 + q0 + tid;
        qy[tid]  = cq[t * 3 + 1];
        qx[tid]  = cq[t * 3 + 2];
        qpd[tid] = qm[t];
    }

    float O[4][4];
    #pragma unroll
    for (int i = 0; i < 4; i++)
        #pragma unroll
        for (int j = 0; j < 4; j++) O[i][j] = 0.f;
    float mrow[4] = {-3.0e38f, -3.0e38f, -3.0e38f, -3.0e38f};
    float lrow[4] = {0.f, 0.f, 0.f, 0.f};

    for (int kt = 0; kt < 9; kt++) {
        const int k0 = kt * 64;
        __syncthreads();  // previous tile consumers done (also covers Q load)

        // K tile (transposed) + k coords/masks
        for (int idx = tid; idx < 4096; idx += 256) {
            int c = idx >> 6, d = idx & 63;
            KVs[d * SSTR + c] = K[(size_t)(tok0 + k0 + c) * D_ + h * 64 + d];
        }
        if (tid < 64) {
            int t = tok0 + k0 + tid;
            kyv[tid] = ck[t * 3 + 1];
            kxv[tid] = ck[t * 3 + 2];
            kpd[tid] = km[t];
        }
        __syncthreads();

        // S = Q K^T (4x4 microtile)
        float s[4][4];
        #pragma unroll
        for (int i = 0; i < 4; i++)
            #pragma unroll
            for (int j = 0; j < 4; j++) s[i][j] = 0.f;
        #pragma unroll 8
        for (int kk = 0; kk < 64; kk++) {
            float4 qv = *(const float4*)&Qs[kk * SSTR + ty * 4];
            float4 kv = *(const float4*)&KVs[kk * SSTR + tx * 4];
            float qa[4] = {qv.x, qv.y, qv.z, qv.w};
            float ka[4] = {kv.x, kv.y, kv.z, kv.w};
            #pragma unroll
            for (int i = 0; i < 4; i++)
                #pragma unroll
                for (int j = 0; j < 4; j++)
                    s[i][j] = fmaf(qa[i], ka[j], s[i][j]);
        }

        // scale + bias
        float rqy[4], rqx[4], rqp[4], cky[4], ckx[4], ckp[4];
        #pragma unroll
        for (int i = 0; i < 4; i++) {
            rqy[i] = qy[ty * 4 + i]; rqx[i] = qx[ty * 4 + i]; rqp[i] = qpd[ty * 4 + i];
        }
        #pragma unroll
        for (int j = 0; j < 4; j++) {
            cky[j] = kyv[tx * 4 + j]; ckx[j] = kxv[tx * 4 + j]; ckp[j] = kpd[tx * 4 + j];
        }
        #pragma unroll
        for (int i = 0; i < 4; i++) {
            #pragma unroll
            for (int j = 0; j < 4; j++) {
                float dy = rqy[i] - cky[j];
                float dx = rqx[i] - ckx[j];
                float dist = sqrtf(dy * dy + dx * dx);
                float cut = (dist > 0.5f) ? NEGBIG : 0.f;
                float bias = cut + alph * __expf(-10.f * dist);
                if (rqp[i] + ckp[j] > 0.f) bias = NEGBIG;
                s[i][j] = s[i][j] * 0.125f + bias;
            }
        }

        // online softmax (row group = 16 lanes within half-warp)
        #pragma unroll
        for (int i = 0; i < 4; i++) {
            float m_ = fmaxf(fmaxf(s[i][0], s[i][1]), fmaxf(s[i][2], s[i][3]));
            m_ = fmaxf(m_, __shfl_xor_sync(0xffffffffu, m_, 1, 16));
            m_ = fmaxf(m_, __shfl_xor_sync(0xffffffffu, m_, 2, 16));
            m_ = fmaxf(m_, __shfl_xor_sync(0xffffffffu, m_, 4, 16));
            m_ = fmaxf(m_, __shfl_xor_sync(0xffffffffu, m_, 8, 16));
            float mn = fmaxf(mrow[i], m_);
            float f = __expf(mrow[i] - mn);
            mrow[i] = mn;
            float ls = 0.f;
            #pragma unroll
            for (int j = 0; j < 4; j++) {
                float p = __expf(s[i][j] - mn);
                s[i][j] = p;
                ls += p;
            }
            ls += __shfl_xor_sync(0xffffffffu, ls, 1, 16);
            ls += __shfl_xor_sync(0xffffffffu, ls, 2, 16);
            ls += __shfl_xor_sync(0xffffffffu, ls, 4, 16);
            ls += __shfl_xor_sync(0xffffffffu, ls, 8, 16);
            lrow[i] = lrow[i] * f + ls;
            #pragma unroll
            for (int j = 0; j < 4; j++) O[i][j] *= f;
        }
        __syncthreads();  // done reading K tile from KVs

        // write P (transposed), load V tile (natural layout)
        #pragma unroll
        for (int i = 0; i < 4; i++)
            #pragma unroll
            for (int j = 0; j < 4; j++)
                Ps[(tx * 4 + j) * SSTR + ty * 4 + i] = s[i][j];
        for (int idx = tid; idx < 4096; idx += 256) {
            int c = idx >> 6, d = idx & 63;
            KVs[c * SSTR + d] = V[(size_t)(tok0 + k0 + c) * D_ + h * 64 + d];
        }
        __syncthreads();

        // O += P V
        #pragma unroll 8
        for (int kk = 0; kk < 64; kk++) {
            float4 pv = *(const float4*)&Ps[kk * SSTR + ty * 4];
            float4 vv = *(const float4*)&KVs[kk * SSTR + tx * 4];
            float pa[4] = {pv.x, pv.y, pv.z, pv.w};
            float va[4] = {vv.x, vv.y, vv.z, vv.w};
            #pragma unroll
            for (int i = 0; i < 4; i++)
                #pragma unroll
                for (int j = 0; j < 4; j++)
                    O[i][j] = fmaf(pa[i], va[j], O[i][j]);
        }
    }

    // epilogue: Y[tok, h*64 + d] = O / l
    #pragma unroll
    for (int i = 0; i < 4; i++) {
        float inv = 1.f / lrow[i];
        float* yp = Y + (size_t)(tok0 + q0 + ty * 4 + i) * D_ + h * 64 + tx * 4;
        float4 r;
        r.x = O[i][0] * inv; r.y = O[i][1] * inv;
        r.z = O[i][2] * inv; r.w = O[i][3] * inv;
        *(float4*)yp = r;
    }
}

// ---------------------------------------------------------------------------
extern "C" void kernel_launch(void* const* d_in, const int* in_sizes, int n_in,
                              void* d_out, int out_size)
{
    (void)in_sizes; (void)n_in; (void)out_size;

    const float*   q_tokens  = (const float*)d_in[0];
    const float*   kv_tokens = (const float*)d_in[1];
    const float*   coords_q  = (const float*)d_in[2];
    const float*   coords_k  = (const float*)d_in[3];
    const void*    q_pad     = d_in[4];
    const void*    kv_pad    = d_in[5];
    const float*   Wq = (const float*)d_in[6];
    const float*   bq = (const float*)d_in[7];
    const float*   Wk = (const float*)d_in[8];
    const float*   bk = (const float*)d_in[9];
    const float*   Wv = (const float*)d_in[10];
    const float*   bv = (const float*)d_in[11];
    const float*   Wo = (const float*)d_in[12];
    const float*   bo = (const float*)d_in[13];
    const float*   alpha = (const float*)d_in[14];
    const float*   f0 = (const float*)d_in[15];
    const float*   f1 = (const float*)d_in[16];
    const float*   f2 = (const float*)d_in[17];
    float* out = (float*)d_out;

    float *Qb, *Kb, *Vb, *Yb, *qmB, *kmB;
    cudaGetSymbolAddress((void**)&Qb, g_Q);
    cudaGetSymbolAddress((void**)&Kb, g_K);
    cudaGetSymbolAddress((void**)&Vb, g_V);
    cudaGetSymbolAddress((void**)&Yb, g_Y);
    cudaGetSymbolAddress((void**)&qmB, g_qm);
    cudaGetSymbolAddress((void**)&kmB, g_km);

    const int attn_smem = (3 * 64 * SSTR + 6 * 64) * (int)sizeof(float);
    cudaFuncSetAttribute(attn_kernel, cudaFuncAttributeMaxDynamicSharedMemorySize,
                         attn_smem);

    // Canonicalize pad masks (dtype-agnostic)
    detect_mask_kernel<<<1, 256>>>((const unsigned*)q_pad, (const unsigned*)kv_pad,
                                   TOK / 4);
    expand_mask_kernel<<<(TOK + 255) / 256, 256>>>(q_pad,  qmB, TOK, 0);
    expand_mask_kernel<<<(TOK + 255) / 256, 256>>>(kv_pad, kmB, TOK, 1);

    dim3 gg(D_ / 128, TOK / 128);  // (8, 36)
    gemm_nt_bias<<<gg, 256>>>(q_tokens,  Wq, bq, Qb, TOK, D_, D_);
    gemm_nt_bias<<<gg, 256>>>(kv_tokens, Wk, bk, Kb, TOK, D_, D_);
    gemm_nt_bias<<<gg, 256>>>(kv_tokens, Wv, bv, Vb, TOK, D_, D_);

    rope_kernel<<<TOK, 128>>>(Qb, coords_q, f0, f1, f2);
    rope_kernel<<<TOK, 128>>>(Kb, coords_k, f0, f1, f2);

    attn_kernel<<<dim3(9, B_ * T_ * H_), 256, attn_smem>>>(
        Qb, Kb, Vb, coords_q, coords_k, qmB, kmB, alpha, Yb);

    gemm_nt_bias<<<gg, 256>>>(Yb, Wo, bo, out, TOK, D_, D_);
}

// round 4
// speedup vs baseline: 1.5303x; 1.5303x over previous
#include <cuda_runtime.h>
#include <cuda_bf16.h>
#include <cstdint>
#include <cstddef>
#include <math.h>

// Problem constants
#define B_   2
#define T_   4
#define NQ_  576
#define NK_  576
#define D_   1024
#define H_   16
#define DH_  64
#define TOK  (B_*T_*NQ_)
#define NEGBIG (-1.7014118e38f)

#define GK 1024
#define GN 1024

// Scratch (device globals; no dynamic allocation allowed)
__device__ float g_Q[TOK * D_];
__device__ float g_K[TOK * D_];
__device__ float g_V[TOK * D_];
__device__ float g_Y[TOK * D_];
__device__ float g_qm[TOK];
__device__ float g_km[TOK];
__device__ int   g_mask_mode[2];

// bf16 hi/lo split operands
__device__ __nv_bfloat16 g_qhi[TOK * D_],  g_qlo[TOK * D_];
__device__ __nv_bfloat16 g_kvhi[TOK * D_], g_kvlo[TOK * D_];
__device__ __nv_bfloat16 g_yhi[TOK * D_],  g_ylo[TOK * D_];
__device__ __nv_bfloat16 g_Wqhi[D_ * D_],  g_Wqlo[D_ * D_];
__device__ __nv_bfloat16 g_Wkhi[D_ * D_],  g_Wklo[D_ * D_];
__device__ __nv_bfloat16 g_Wvhi[D_ * D_],  g_Wvlo[D_ * D_];
__device__ __nv_bfloat16 g_Wohi[D_ * D_],  g_Wolo[D_ * D_];

// ---------------------------------------------------------------------------
// Family-portable PTX helpers (compile for compute_103 plain)
// ---------------------------------------------------------------------------
__device__ __forceinline__ uint32_t smem_u32(const void* p) {
    uint32_t a;
    asm("{ .reg .u64 t; cvta.to.shared.u64 t, %1; cvt.u32.u64 %0, t; }"
        : "=r"(a) : "l"(p));
    return a;
}
__device__ __forceinline__ void cp16(uint32_t s, const void* g) {
    asm volatile("cp.async.cg.shared.global [%0], [%1], 16;"
                 :: "r"(s), "l"(g) : "memory");
}
__device__ __forceinline__ void cp_commit() {
    asm volatile("cp.async.commit_group;" ::: "memory");
}
__device__ __forceinline__ void cp_wait1() {
    asm volatile("cp.async.wait_group 1;" ::: "memory");
}
__device__ __forceinline__ void cp_wait0() {
    asm volatile("cp.async.wait_group 0;" ::: "memory");
}
__device__ __forceinline__ void ldm_x4(uint32_t* r, uint32_t addr) {
    asm volatile("ldmatrix.sync.aligned.m8n8.x4.shared.b16 {%0,%1,%2,%3}, [%4];"
                 : "=r"(r[0]), "=r"(r[1]), "=r"(r[2]), "=r"(r[3]) : "r"(addr));
}
__device__ __forceinline__ void mma_bf16(float* d, const uint32_t* a, const uint32_t* b) {
    asm volatile(
        "mma.sync.aligned.m16n8k16.row.col.f32.bf16.bf16.f32 "
        "{%0,%1,%2,%3}, {%4,%5,%6,%7}, {%8,%9}, {%0,%1,%2,%3};"
        : "+f"(d[0]), "+f"(d[1]), "+f"(d[2]), "+f"(d[3])
        : "r"(a[0]), "r"(a[1]), "r"(a[2]), "r"(a[3]), "r"(b[0]), "r"(b[1]));
}

// ---------------------------------------------------------------------------
// fp32 -> bf16 hi/lo split (vectorized by 4)
// ---------------------------------------------------------------------------
__global__ void split_bf16_kernel(const float* __restrict__ x,
                                  __nv_bfloat16* __restrict__ hi,
                                  __nv_bfloat16* __restrict__ lo, int n4)
{
    int i = blockIdx.x * blockDim.x + threadIdx.x;
    if (i >= n4) return;
    float4 v = ((const float4*)x)[i];
    __nv_bfloat16 h0 = __float2bfloat16(v.x);
    __nv_bfloat16 h1 = __float2bfloat16(v.y);
    __nv_bfloat16 h2 = __float2bfloat16(v.z);
    __nv_bfloat16 h3 = __float2bfloat16(v.w);
    __nv_bfloat16 l0 = __float2bfloat16(v.x - __bfloat162float(h0));
    __nv_bfloat16 l1 = __float2bfloat16(v.y - __bfloat162float(h1));
    __nv_bfloat16 l2 = __float2bfloat16(v.z - __bfloat162float(h2));
    __nv_bfloat16 l3 = __float2bfloat16(v.w - __bfloat162float(h3));
    ((__nv_bfloat162*)hi)[2*i]   = __nv_bfloat162(h0, h1);
    ((__nv_bfloat162*)hi)[2*i+1] = __nv_bfloat162(h2, h3);
    ((__nv_bfloat162*)lo)[2*i]   = __nv_bfloat162(l0, l1);
    ((__nv_bfloat162*)lo)[2*i+1] = __nv_bfloat162(l2, l3);
}

// ---------------------------------------------------------------------------
// HMMA GEMM: C[M,GN] = Afp32 @ Wfp32^T + bias via bf16 3-pass split.
// CTA 128x128, k-chunks of 32 bf16 (64B rows padded to 80B), cp.async
// double-buffered, 8 warps (2m x 4n), warp tile 64x32, mma.m16n8k16.
// ---------------------------------------------------------------------------
#define TILE_B 10240            // 128 rows * 80 B
#define GBUF   (2 * TILE_B)     // A + B tiles per buffer
#define NCH    96               // 3 passes * 32 k-chunks

__global__ void __launch_bounds__(256)
gemm_mma(const __nv_bfloat16* __restrict__ Ahi, const __nv_bfloat16* __restrict__ Alo,
         const __nv_bfloat16* __restrict__ Bhi, const __nv_bfloat16* __restrict__ Blo,
         const float* __restrict__ bias, float* __restrict__ C)
{
    extern __shared__ char dsm[];
    const uint32_t sbase = smem_u32(dsm);

    const int tid  = threadIdx.x;
    const int wid  = tid >> 5;
    const int lane = tid & 31;
    const int m0 = blockIdx.y * 128;
    const int n0 = blockIdx.x * 128;
    const int wm = (wid & 1) * 64;
    const int wn = (wid >> 1) * 32;

    float acc[4][4][4];
    #pragma unroll
    for (int mt = 0; mt < 4; mt++)
        #pragma unroll
        for (int nt = 0; nt < 4; nt++)
            #pragma unroll
            for (int r = 0; r < 4; r++) acc[mt][nt][r] = 0.f;

    // per-thread load slots: idx in [0,1024): tile(A/B), row, 16B chunk
    const int l_tl[4]  = { (tid + 0) >> 9, (tid + 256) >> 9, (tid + 512) >> 9, (tid + 768) >> 9 };
    int l_row[4], l_c[4];
    #pragma unroll
    for (int j = 0; j < 4; j++) {
        int i = (tid + j * 256) & 511;
        l_row[j] = i >> 2;
        l_c[j]   = i & 3;
    }

    auto issue_load = [&](int ch, int buf) {
        const int p = ch >> 5;
        const int k0 = (ch & 31) * 32;
        const __nv_bfloat16* As = (p == 1) ? Alo : Ahi;
        const __nv_bfloat16* Bs = (p == 2) ? Blo : Bhi;
        #pragma unroll
        for (int j = 0; j < 4; j++) {
            const __nv_bfloat16* g = l_tl[j]
                ? Bs + (size_t)(n0 + l_row[j]) * GK + k0 + l_c[j] * 8
                : As + (size_t)(m0 + l_row[j]) * GK + k0 + l_c[j] * 8;
            uint32_t s = sbase + buf * GBUF + l_tl[j] * TILE_B
                       + l_row[j] * 80 + l_c[j] * 16;
            cp16(s, g);
        }
        cp_commit();
    };

    issue_load(0, 0);

    for (int ch = 0; ch < NCH; ch++) {
        if (ch + 1 < NCH) { issue_load(ch + 1, (ch + 1) & 1); cp_wait1(); }
        else              { cp_wait0(); }
        __syncthreads();

        const uint32_t abase = sbase + (ch & 1) * GBUF;
        const uint32_t bbase = abase + TILE_B;

        #pragma unroll
        for (int ks = 0; ks < 2; ks++) {
            uint32_t a[4][4], b[4][2];
            #pragma unroll
            for (int mt = 0; mt < 4; mt++) {
                uint32_t addr = abase + (wm + mt * 16 + (lane & 15)) * 80
                              + (lane >> 4) * 16 + ks * 32;
                ldm_x4(a[mt], addr);
            }
            #pragma unroll
            for (int np = 0; np < 2; np++) {
                uint32_t addr = bbase
                    + (wn + np * 16 + (lane & 7) + ((lane >> 4) & 1) * 8) * 80
                    + ((lane >> 3) & 1) * 16 + ks * 32;
                uint32_t r[4];
                ldm_x4(r, addr);
                b[np * 2][0] = r[0];     b[np * 2][1] = r[1];
                b[np * 2 + 1][0] = r[2]; b[np * 2 + 1][1] = r[3];
            }
            #pragma unroll
            for (int mt = 0; mt < 4; mt++)
                #pragma unroll
                for (int nt = 0; nt < 4; nt++)
                    mma_bf16(acc[mt][nt], a[mt], b[nt]);
        }
        __syncthreads();
    }

    // epilogue: +bias, write fp32
    const int cbase = n0 + wn + (lane & 3) * 2;
    float bv[4][2];
    #pragma unroll
    for (int nt = 0; nt < 4; nt++) {
        bv[nt][0] = bias[cbase + nt * 8];
        bv[nt][1] = bias[cbase + nt * 8 + 1];
    }
    #pragma unroll
    for (int mt = 0; mt < 4; mt++) {
        int r0 = m0 + wm + mt * 16 + (lane >> 2);
        #pragma unroll
        for (int nt = 0; nt < 4; nt++) {
            int c = cbase + nt * 8;
            float2 v0 = { acc[mt][nt][0] + bv[nt][0], acc[mt][nt][1] + bv[nt][1] };
            float2 v1 = { acc[mt][nt][2] + bv[nt][0], acc[mt][nt][3] + bv[nt][1] };
            *(float2*)&C[(size_t)r0 * GN + c]       = v0;
            *(float2*)&C[(size_t)(r0 + 8) * GN + c] = v1;
        }
    }
}

// ---------------------------------------------------------------------------
// Mask dtype detection + expansion
// ---------------------------------------------------------------------------
__global__ void detect_mask_kernel(const unsigned* __restrict__ qm,
                                   const unsigned* __restrict__ km, int nints)
{
    __shared__ int s_i, s_f;
    for (int b = 0; b < 2; b++) {
        if (threadIdx.x == 0) { s_i = 1; s_f = 1; }
        __syncthreads();
        const unsigned* p = b ? km : qm;
        int li = 1, lf = 1;
        for (int i = threadIdx.x; i < nints; i += blockDim.x) {
            unsigned v = p[i];
            if (v > 1u) li = 0;
            if (v != 0u && v != 0x3f800000u) lf = 0;
        }
        if (!li) atomicAnd(&s_i, 0);
        if (!lf) atomicAnd(&s_f, 0);
        __syncthreads();
        if (threadIdx.x == 0)
            g_mask_mode[b] = s_i ? 1 : (s_f ? 2 : 0);
        __syncthreads();
    }
}

__global__ void expand_mask_kernel(const void* __restrict__ src,
                                   float* __restrict__ dst, int n, int which)
{
    int mode = g_mask_mode[which];
    int i = blockIdx.x * blockDim.x + threadIdx.x;
    if (i >= n) return;
    bool m;
    if (mode == 1)      m = ((const int*)src)[i] != 0;
    else if (mode == 2) m = ((const float*)src)[i] != 0.f;
    else                m = ((const unsigned char*)src)[i] != 0;
    dst[i] = m ? 1.f : 0.f;
}

// ---------------------------------------------------------------------------
// 4D RoPE
// ---------------------------------------------------------------------------
__global__ void rope_kernel(float* __restrict__ X, const float* __restrict__ coords,
                            const float* __restrict__ f0, const float* __restrict__ f1,
                            const float* __restrict__ f2)
{
    __shared__ float cs[32], sn[32];
    const int tok = blockIdx.x;
    const int tid = threadIdx.x;

    if (tid < 32) {
        float coord, fr;
        if (tid < 12)      { coord = coords[tok * 3 + 0]; fr = f0[tid]; }
        else if (tid < 22) { coord = coords[tok * 3 + 1]; fr = f1[tid - 12]; }
        else               { coord = coords[tok * 3 + 2]; fr = f2[tid - 22]; }
        float arg = 1.5707963267948966f * coord * fr;
        float s, c;
        sincosf(arg, &s, &c);
        sn[tid] = s; cs[tid] = c;
    }
    __syncthreads();

    float* xp = X + (size_t)tok * D_;
    for (int p = tid; p < H_ * 32; p += blockDim.x) {
        int h = p >> 5, j = p & 31;
        int idx = h * 64 + j * 2;
        float x0 = xp[idx], x1 = xp[idx + 1];
        float c = cs[j], s = sn[j];
        xp[idx]     = x0 * c - x1 * s;
        xp[idx + 1] = x1 * c + x0 * s;
    }
}

// ---------------------------------------------------------------------------
// Flash-style attention (fp32), 64-query block, fused distance bias.
// ---------------------------------------------------------------------------
#define SSTR 68

__global__ void __launch_bounds__(256)
attn_kernel(const float* __restrict__ Q, const float* __restrict__ K,
            const float* __restrict__ V,
            const float* __restrict__ cq, const float* __restrict__ ck,
            const float* __restrict__ qm, const float* __restrict__ km,
            const float* __restrict__ alpha, float* __restrict__ Y)
{
    extern __shared__ float smem[];
    float* Qs  = smem;
    float* KVs = smem + 64 * SSTR;
    float* Ps  = smem + 2 * 64 * SSTR;
    float* qy  = smem + 3 * 64 * SSTR;
    float* qx  = qy + 64;
    float* kyv = qx + 64;
    float* kxv = kyv + 64;
    float* qpd = kxv + 64;
    float* kpd = qpd + 64;

    const int tid = threadIdx.x;
    const int tx = tid & 15, ty = tid >> 4;
    const int qb = blockIdx.x;
    const int h  = blockIdx.y & 15;
    const int bt = blockIdx.y >> 4;
    const int tok0 = bt * NQ_;
    const float alph = alpha[h];
    const int q0 = qb * 64;

    for (int idx = tid; idx < 4096; idx += 256) {
        int r = idx >> 6, d = idx & 63;
        Qs[d * SSTR + r] = Q[(size_t)(tok0 + q0 + r) * D_ + h * 64 + d];
    }
    if (tid < 64) {
        int t = tok0 + q0 + tid;
        qy[tid]  = cq[t * 3 + 1];
        qx[tid]  = cq[t * 3 + 2];
        qpd[tid] = qm[t];
    }

    float O[4][4];
    #pragma unroll
    for (int i = 0; i < 4; i++)
        #pragma unroll
        for (int j = 0; j < 4; j++) O[i][j] = 0.f;
    float mrow[4] = {-3.0e38f, -3.0e38f, -3.0e38f, -3.0e38f};
    float lrow[4] = {0.f, 0.f, 0.f, 0.f};

    for (int kt = 0; kt < 9; kt++) {
        const int k0 = kt * 64;
        __syncthreads();

        for (int idx = tid; idx < 4096; idx += 256) {
            int c = idx >> 6, d = idx & 63;
            KVs[d * SSTR + c] = K[(size_t)(tok0 + k0 + c) * D_ + h * 64 + d];
        }
        if (tid < 64) {
            int t = tok0 + k0 + tid;
            kyv[tid] = ck[t * 3 + 1];
            kxv[tid] = ck[t * 3 + 2];
            kpd[tid] = km[t];
        }
        __syncthreads();

        float s[4][4];
        #pragma unroll
        for (int i = 0; i < 4; i++)
            #pragma unroll
            for (int j = 0; j < 4; j++) s[i][j] = 0.f;
        #pragma unroll 8
        for (int kk = 0; kk < 64; kk++) {
            float4 qv = *(const float4*)&Qs[kk * SSTR + ty * 4];
            float4 kv = *(const float4*)&KVs[kk * SSTR + tx * 4];
            float qa[4] = {qv.x, qv.y, qv.z, qv.w};
            float ka[4] = {kv.x, kv.y, kv.z, kv.w};
            #pragma unroll
            for (int i = 0; i < 4; i++)
                #pragma unroll
                for (int j = 0; j < 4; j++)
                    s[i][j] = fmaf(qa[i], ka[j], s[i][j]);
        }

        float rqy[4], rqx[4], rqp[4], cky[4], ckx[4], ckp[4];
        #pragma unroll
        for (int i = 0; i < 4; i++) {
            rqy[i] = qy[ty * 4 + i]; rqx[i] = qx[ty * 4 + i]; rqp[i] = qpd[ty * 4 + i];
        }
        #pragma unroll
        for (int j = 0; j < 4; j++) {
            cky[j] = kyv[tx * 4 + j]; ckx[j] = kxv[tx * 4 + j]; ckp[j] = kpd[tx * 4 + j];
        }
        #pragma unroll
        for (int i = 0; i < 4; i++) {
            #pragma unroll
            for (int j = 0; j < 4; j++) {
                float dy = rqy[i] - cky[j];
                float dx = rqx[i] - ckx[j];
                float dist = sqrtf(dy * dy + dx * dx);
                float cut = (dist > 0.5f) ? NEGBIG : 0.f;
                float bias = cut + alph * __expf(-10.f * dist);
                if (rqp[i] + ckp[j] > 0.f) bias = NEGBIG;
                s[i][j] = s[i][j] * 0.125f + bias;
            }
        }

        #pragma unroll
        for (int i = 0; i < 4; i++) {
            float m_ = fmaxf(fmaxf(s[i][0], s[i][1]), fmaxf(s[i][2], s[i][3]));
            m_ = fmaxf(m_, __shfl_xor_sync(0xffffffffu, m_, 1, 16));
            m_ = fmaxf(m_, __shfl_xor_sync(0xffffffffu, m_, 2, 16));
            m_ = fmaxf(m_, __shfl_xor_sync(0xffffffffu, m_, 4, 16));
            m_ = fmaxf(m_, __shfl_xor_sync(0xffffffffu, m_, 8, 16));
            float mn = fmaxf(mrow[i], m_);
            float f = __expf(mrow[i] - mn);
            mrow[i] = mn;
            float ls = 0.f;
            #pragma unroll
            for (int j = 0; j < 4; j++) {
                float p = __expf(s[i][j] - mn);
                s[i][j] = p;
                ls += p;
            }
            ls += __shfl_xor_sync(0xffffffffu, ls, 1, 16);
            ls += __shfl_xor_sync(0xffffffffu, ls, 2, 16);
            ls += __shfl_xor_sync(0xffffffffu, ls, 4, 16);
            ls += __shfl_xor_sync(0xffffffffu, ls, 8, 16);
            lrow[i] = lrow[i] * f + ls;
            #pragma unroll
            for (int j = 0; j < 4; j++) O[i][j] *= f;
        }
        __syncthreads();

        #pragma unroll
        for (int i = 0; i < 4; i++)
            #pragma unroll
            for (int j = 0; j < 4; j++)
                Ps[(tx * 4 + j) * SSTR + ty * 4 + i] = s[i][j];
        for (int idx = tid; idx < 4096; idx += 256) {
            int c = idx >> 6, d = idx & 63;
            KVs[c * SSTR + d] = V[(size_t)(tok0 + k0 + c) * D_ + h * 64 + d];
        }
        __syncthreads();

        #pragma unroll 8
        for (int kk = 0; kk < 64; kk++) {
            float4 pv = *(const float4*)&Ps[kk * SSTR + ty * 4];
            float4 vv = *(const float4*)&KVs[kk * SSTR + tx * 4];
            float pa[4] = {pv.x, pv.y, pv.z, pv.w};
            float va[4] = {vv.x, vv.y, vv.z, vv.w};
            #pragma unroll
            for (int i = 0; i < 4; i++)
                #pragma unroll
                for (int j = 0; j < 4; j++)
                    O[i][j] = fmaf(pa[i], va[j], O[i][j]);
        }
    }

    #pragma unroll
    for (int i = 0; i < 4; i++) {
        float inv = 1.f / lrow[i];
        float* yp = Y + (size_t)(tok0 + q0 + ty * 4 + i) * D_ + h * 64 + tx * 4;
        float4 r;
        r.x = O[i][0] * inv; r.y = O[i][1] * inv;
        r.z = O[i][2] * inv; r.w = O[i][3] * inv;
        *(float4*)yp = r;
    }
}

// ---------------------------------------------------------------------------
extern "C" void kernel_launch(void* const* d_in, const int* in_sizes, int n_in,
                              void* d_out, int out_size)
{
    (void)in_sizes; (void)n_in; (void)out_size;

    const float*   q_tokens  = (const float*)d_in[0];
    const float*   kv_tokens = (const float*)d_in[1];
    const float*   coords_q  = (const float*)d_in[2];
    const float*   coords_k  = (const float*)d_in[3];
    const void*    q_pad     = d_in[4];
    const void*    kv_pad    = d_in[5];
    const float*   Wq = (const float*)d_in[6];
    const float*   bq = (const float*)d_in[7];
    const float*   Wk = (const float*)d_in[8];
    const float*   bk = (const float*)d_in[9];
    const float*   Wv = (const float*)d_in[10];
    const float*   bv = (const float*)d_in[11];
    const float*   Wo = (const float*)d_in[12];
    const float*   bo = (const float*)d_in[13];
    const float*   alpha = (const float*)d_in[14];
    const float*   f0 = (const float*)d_in[15];
    const float*   f1 = (const float*)d_in[16];
    const float*   f2 = (const float*)d_in[17];
    float* out = (float*)d_out;

    float *Qb, *Kb, *Vb, *Yb, *qmB, *kmB;
    cudaGetSymbolAddress((void**)&Qb, g_Q);
    cudaGetSymbolAddress((void**)&Kb, g_K);
    cudaGetSymbolAddress((void**)&Vb, g_V);
    cudaGetSymbolAddress((void**)&Yb, g_Y);
    cudaGetSymbolAddress((void**)&qmB, g_qm);
    cudaGetSymbolAddress((void**)&kmB, g_km);

    __nv_bfloat16 *qhi, *qlo, *kvhi, *kvlo, *yhi, *ylo;
    __nv_bfloat16 *Wqhi, *Wqlo, *Wkhi, *Wklo, *Wvhi, *Wvlo, *Wohi, *Wolo;
    cudaGetSymbolAddress((void**)&qhi,  g_qhi);  cudaGetSymbolAddress((void**)&qlo,  g_qlo);
    cudaGetSymbolAddress((void**)&kvhi, g_kvhi); cudaGetSymbolAddress((void**)&kvlo, g_kvlo);
    cudaGetSymbolAddress((void**)&yhi,  g_yhi);  cudaGetSymbolAddress((void**)&ylo,  g_ylo);
    cudaGetSymbolAddress((void**)&Wqhi, g_Wqhi); cudaGetSymbolAddress((void**)&Wqlo, g_Wqlo);
    cudaGetSymbolAddress((void**)&Wkhi, g_Wkhi); cudaGetSymbolAddress((void**)&Wklo, g_Wklo);
    cudaGetSymbolAddress((void**)&Wvhi, g_Wvhi); cudaGetSymbolAddress((void**)&Wvlo, g_Wvlo);
    cudaGetSymbolAddress((void**)&Wohi, g_Wohi); cudaGetSymbolAddress((void**)&Wolo, g_Wolo);

    const int attn_smem = (3 * 64 * SSTR + 6 * 64) * (int)sizeof(float);
    cudaFuncSetAttribute(attn_kernel, cudaFuncAttributeMaxDynamicSharedMemorySize,
                         attn_smem);
    const int gemm_smem = 2 * GBUF;  // 40960 bytes
    cudaFuncSetAttribute(gemm_mma, cudaFuncAttributeMaxDynamicSharedMemorySize,
                         gemm_smem);

    // Canonicalize pad masks (dtype-agnostic)
    detect_mask_kernel<<<1, 256>>>((const unsigned*)q_pad, (const unsigned*)kv_pad,
                                   TOK / 4);
    expand_mask_kernel<<<(TOK + 255) / 256, 256>>>(q_pad,  qmB, TOK, 0);
    expand_mask_kernel<<<(TOK + 255) / 256, 256>>>(kv_pad, kmB, TOK, 1);

    // bf16 hi/lo splits for activations and weights
    const int ntok4 = TOK * D_ / 4, nw4 = D_ * D_ / 4;
    split_bf16_kernel<<<(ntok4 + 255) / 256, 256>>>(q_tokens,  qhi,  qlo,  ntok4);
    split_bf16_kernel<<<(ntok4 + 255) / 256, 256>>>(kv_tokens, kvhi, kvlo, ntok4);
    split_bf16_kernel<<<(nw4 + 255) / 256, 256>>>(Wq, Wqhi, Wqlo, nw4);
    split_bf16_kernel<<<(nw4 + 255) / 256, 256>>>(Wk, Wkhi, Wklo, nw4);
    split_bf16_kernel<<<(nw4 + 255) / 256, 256>>>(Wv, Wvhi, Wvlo, nw4);
    split_bf16_kernel<<<(nw4 + 255) / 256, 256>>>(Wo, Wohi, Wolo, nw4);

    dim3 gg(GN / 128, TOK / 128);  // (8, 36)
    gemm_mma<<<gg, 256, gemm_smem>>>(qhi,  qlo,  Wqhi, Wqlo, bq, Qb);
    gemm_mma<<<gg, 256, gemm_smem>>>(kvhi, kvlo, Wkhi, Wklo, bk, Kb);
    gemm_mma<<<gg, 256, gemm_smem>>>(kvhi, kvlo, Wvhi, Wvlo, bv, Vb);

    rope_kernel<<<TOK, 128>>>(Qb, coords_q, f0, f1, f2);
    rope_kernel<<<TOK, 128>>>(Kb, coords_k, f0, f1, f2);

    attn_kernel<<<dim3(9, B_ * T_ * H_), 256, attn_smem>>>(
        Qb, Kb, Vb, coords_q, coords_k, qmB, kmB, alpha, Yb);

    split_bf16_kernel<<<(ntok4 + 255) / 256, 256>>>(Yb, yhi, ylo, ntok4);
    gemm_mma<<<gg, 256, gemm_smem>>>(yhi, ylo, Wohi, Wolo, bo, out);
}

// round 5
// speedup vs baseline: 1.9417x; 1.2688x over previous
#include <cuda_runtime.h>
#include <cuda_bf16.h>
#include <cstdint>
#include <cstddef>
#include <math.h>

// Problem constants
#define B_   2
#define T_   4
#define NQ_  576
#define NK_  576
#define D_   1024
#define H_   16
#define DH_  64
#define TOK  (B_*T_*NQ_)
#define NEGBIG (-1.7014118e38f)
#define LOG2E 1.4426950408889634f

#define GK 1024
#define GN 1024

// Scratch (device globals; no dynamic allocation allowed)
__device__ float g_Q[TOK * D_];
__device__ float g_K[TOK * D_];
__device__ float g_V[TOK * D_];
__device__ float g_Y[TOK * D_];
__device__ float g_qm[TOK];
__device__ float g_km[TOK];
__device__ int   g_mask_mode[2];
__device__ float g_E[8 * NQ_ * NK_];          // fused bias: prior or -3e38

// bf16 hi/lo split operands (projection inputs)
__device__ __nv_bfloat16 g_qhi[TOK * D_],  g_qlo[TOK * D_];
__device__ __nv_bfloat16 g_kvhi[TOK * D_], g_kvlo[TOK * D_];
__device__ __nv_bfloat16 g_yhi[TOK * D_],  g_ylo[TOK * D_];
__device__ __nv_bfloat16 g_Wqhi[D_ * D_],  g_Wqlo[D_ * D_];
__device__ __nv_bfloat16 g_Wkhi[D_ * D_],  g_Wklo[D_ * D_];
__device__ __nv_bfloat16 g_Wvhi[D_ * D_],  g_Wvlo[D_ * D_];
__device__ __nv_bfloat16 g_Wohi[D_ * D_],  g_Wolo[D_ * D_];

// attention operands (post-rope splits)
__device__ __nv_bfloat16 g_aQh[TOK * D_], g_aQl[TOK * D_];
__device__ __nv_bfloat16 g_aKh[TOK * D_], g_aKl[TOK * D_];
__device__ __nv_bfloat16 g_vth[128 * 64 * NK_], g_vtl[128 * 64 * NK_]; // V^T per (f,h)

// ---------------------------------------------------------------------------
// Family-portable PTX helpers
// ---------------------------------------------------------------------------
__device__ __forceinline__ uint32_t smem_u32(const void* p) {
    uint32_t a;
    asm("{ .reg .u64 t; cvta.to.shared.u64 t, %1; cvt.u32.u64 %0, t; }"
        : "=r"(a) : "l"(p));
    return a;
}
__device__ __forceinline__ void cp16(uint32_t s, const void* g) {
    asm volatile("cp.async.cg.shared.global [%0], [%1], 16;"
                 :: "r"(s), "l"(g) : "memory");
}
__device__ __forceinline__ void cp_commit() {
    asm volatile("cp.async.commit_group;" ::: "memory");
}
__device__ __forceinline__ void cp_wait1() {
    asm volatile("cp.async.wait_group 1;" ::: "memory");
}
__device__ __forceinline__ void cp_wait0() {
    asm volatile("cp.async.wait_group 0;" ::: "memory");
}
__device__ __forceinline__ void ldm_x4(uint32_t* r, uint32_t addr) {
    asm volatile("ldmatrix.sync.aligned.m8n8.x4.shared.b16 {%0,%1,%2,%3}, [%4];"
                 : "=r"(r[0]), "=r"(r[1]), "=r"(r[2]), "=r"(r[3]) : "r"(addr));
}
__device__ __forceinline__ void mma_bf16(float* d, const uint32_t* a, const uint32_t* b) {
    asm volatile(
        "mma.sync.aligned.m16n8k16.row.col.f32.bf16.bf16.f32 "
        "{%0,%1,%2,%3}, {%4,%5,%6,%7}, {%8,%9}, {%0,%1,%2,%3};"
        : "+f"(d[0]), "+f"(d[1]), "+f"(d[2]), "+f"(d[3])
        : "r"(a[0]), "r"(a[1]), "r"(a[2]), "r"(a[3]), "r"(b[0]), "r"(b[1]));
}
__device__ __forceinline__ float ex2(float x) {
    float y;
    asm("ex2.approx.f32 %0, %1;" : "=f"(y) : "f"(x));
    return y;
}

// ---------------------------------------------------------------------------
// fp32 -> bf16 hi/lo split (vectorized by 4)
// ---------------------------------------------------------------------------
__global__ void split_bf16_kernel(const float* __restrict__ x,
                                  __nv_bfloat16* __restrict__ hi,
                                  __nv_bfloat16* __restrict__ lo, int n4)
{
    int i = blockIdx.x * blockDim.x + threadIdx.x;
    if (i >= n4) return;
    float4 v = ((const float4*)x)[i];
    __nv_bfloat16 h0 = __float2bfloat16(v.x);
    __nv_bfloat16 h1 = __float2bfloat16(v.y);
    __nv_bfloat16 h2 = __float2bfloat16(v.z);
    __nv_bfloat16 h3 = __float2bfloat16(v.w);
    __nv_bfloat16 l0 = __float2bfloat16(v.x - __bfloat162float(h0));
    __nv_bfloat16 l1 = __float2bfloat16(v.y - __bfloat162float(h1));
    __nv_bfloat16 l2 = __float2bfloat16(v.z - __bfloat162float(h2));
    __nv_bfloat16 l3 = __float2bfloat16(v.w - __bfloat162float(h3));
    ((__nv_bfloat162*)hi)[2*i]   = __nv_bfloat162(h0, h1);
    ((__nv_bfloat162*)hi)[2*i+1] = __nv_bfloat162(h2, h3);
    ((__nv_bfloat162*)lo)[2*i]   = __nv_bfloat162(l0, l1);
    ((__nv_bfloat162*)lo)[2*i+1] = __nv_bfloat162(l2, l3);
}

// ---------------------------------------------------------------------------
// V transpose + split: g_V[f*576+key][d] -> vth/vtl[(f*16+h)*64+dl][key]
// ---------------------------------------------------------------------------
__global__ void vtsplit_kernel(const float* __restrict__ V,
                               __nv_bfloat16* __restrict__ vh,
                               __nv_bfloat16* __restrict__ vl)
{
    __shared__ float t[32][33];
    const int k0 = blockIdx.x * 32, d0 = blockIdx.y * 32, f = blockIdx.z;
    const int tx = threadIdx.x & 31, ty = threadIdx.x >> 5;
    #pragma unroll
    for (int i = 0; i < 4; i++) {
        int key = k0 + ty + i * 8;
        t[ty + i * 8][tx] = V[(size_t)(f * NQ_ + key) * D_ + d0 + tx];
    }
    __syncthreads();
    #pragma unroll
    for (int i = 0; i < 4; i++) {
        int dd = ty + i * 8;
        int d = d0 + dd, h = d >> 6, dl = d & 63;
        float v = t[tx][dd];
        __nv_bfloat16 hi = __float2bfloat16(v);
        __nv_bfloat16 lo = __float2bfloat16(v - __bfloat162float(hi));
        size_t oi = ((size_t)(f * 16 + h) * 64 + dl) * NK_ + k0 + tx;
        vh[oi] = hi;
        vl[oi] = lo;
    }
}

// ---------------------------------------------------------------------------
// Fused bias precompute: E[f][q][k] = masked ? -3e38 : exp(-10*dist)
// (head-independent; shared across all 16 heads)
// ---------------------------------------------------------------------------
__global__ void bias_kernel(const float* __restrict__ cq, const float* __restrict__ ck,
                            const float* __restrict__ qm, const float* __restrict__ km,
                            float* __restrict__ E)
{
    const int q = blockIdx.x, f = blockIdx.y, k = threadIdx.x;
    const int qi = f * NQ_ + q, ki = f * NK_ + k;
    float qy = cq[qi * 3 + 1], qx = cq[qi * 3 + 2];
    float dy = qy - ck[ki * 3 + 1];
    float dx = qx - ck[ki * 3 + 2];
    float dist = sqrtf(dy * dy + dx * dx);
    bool bad = (qm[qi] + km[ki] > 0.f) || (dist > 0.5f);
    E[(size_t)qi * NK_ + k] = bad ? -3.0e38f : __expf(-10.f * dist);
}

// ---------------------------------------------------------------------------
// HMMA GEMM (unchanged from round 4): 3-pass bf16 split, 128x128 CTA tile.
// ---------------------------------------------------------------------------
#define TILE_B 10240
#define GBUF   (2 * TILE_B)
#define NCH    96

__global__ void __launch_bounds__(256)
gemm_mma(const __nv_bfloat16* __restrict__ Ahi, const __nv_bfloat16* __restrict__ Alo,
         const __nv_bfloat16* __restrict__ Bhi, const __nv_bfloat16* __restrict__ Blo,
         const float* __restrict__ bias, float* __restrict__ C)
{
    extern __shared__ char dsm[];
    const uint32_t sbase = smem_u32(dsm);

    const int tid  = threadIdx.x;
    const int wid  = tid >> 5;
    const int lane = tid & 31;
    const int m0 = blockIdx.y * 128;
    const int n0 = blockIdx.x * 128;
    const int wm = (wid & 1) * 64;
    const int wn = (wid >> 1) * 32;

    float acc[4][4][4];
    #pragma unroll
    for (int mt = 0; mt < 4; mt++)
        #pragma unroll
        for (int nt = 0; nt < 4; nt++)
            #pragma unroll
            for (int r = 0; r < 4; r++) acc[mt][nt][r] = 0.f;

    const int l_tl[4]  = { (tid + 0) >> 9, (tid + 256) >> 9, (tid + 512) >> 9, (tid + 768) >> 9 };
    int l_row[4], l_c[4];
    #pragma unroll
    for (int j = 0; j < 4; j++) {
        int i = (tid + j * 256) & 511;
        l_row[j] = i >> 2;
        l_c[j]   = i & 3;
    }

    auto issue_load = [&](int ch, int buf) {
        const int p = ch >> 5;
        const int k0 = (ch & 31) * 32;
        const __nv_bfloat16* As = (p == 1) ? Alo : Ahi;
        const __nv_bfloat16* Bs = (p == 2) ? Blo : Bhi;
        #pragma unroll
        for (int j = 0; j < 4; j++) {
            const __nv_bfloat16* g = l_tl[j]
                ? Bs + (size_t)(n0 + l_row[j]) * GK + k0 + l_c[j] * 8
                : As + (size_t)(m0 + l_row[j]) * GK + k0 + l_c[j] * 8;
            uint32_t s = sbase + buf * GBUF + l_tl[j] * TILE_B
                       + l_row[j] * 80 + l_c[j] * 16;
            cp16(s, g);
        }
        cp_commit();
    };

    issue_load(0, 0);

    for (int ch = 0; ch < NCH; ch++) {
        if (ch + 1 < NCH) { issue_load(ch + 1, (ch + 1) & 1); cp_wait1(); }
        else              { cp_wait0(); }
        __syncthreads();

        const uint32_t abase = sbase + (ch & 1) * GBUF;
        const uint32_t bbase = abase + TILE_B;

        #pragma unroll
        for (int ks = 0; ks < 2; ks++) {
            uint32_t a[4][4], b[4][2];
            #pragma unroll
            for (int mt = 0; mt < 4; mt++) {
                uint32_t addr = abase + (wm + mt * 16 + (lane & 15)) * 80
                              + (lane >> 4) * 16 + ks * 32;
                ldm_x4(a[mt], addr);
            }
            #pragma unroll
            for (int np = 0; np < 2; np++) {
                uint32_t addr = bbase
                    + (wn + np * 16 + (lane & 7) + ((lane >> 4) & 1) * 8) * 80
                    + ((lane >> 3) & 1) * 16 + ks * 32;
                uint32_t r[4];
                ldm_x4(r, addr);
                b[np * 2][0] = r[0];     b[np * 2][1] = r[1];
                b[np * 2 + 1][0] = r[2]; b[np * 2 + 1][1] = r[3];
            }
            #pragma unroll
            for (int mt = 0; mt < 4; mt++)
                #pragma unroll
                for (int nt = 0; nt < 4; nt++)
                    mma_bf16(acc[mt][nt], a[mt], b[nt]);
        }
        __syncthreads();
    }

    const int cbase = n0 + wn + (lane & 3) * 2;
    float bv[4][2];
    #pragma unroll
    for (int nt = 0; nt < 4; nt++) {
        bv[nt][0] = bias[cbase + nt * 8];
        bv[nt][1] = bias[cbase + nt * 8 + 1];
    }
    #pragma unroll
    for (int mt = 0; mt < 4; mt++) {
        int r0 = m0 + wm + mt * 16 + (lane >> 2);
        #pragma unroll
        for (int nt = 0; nt < 4; nt++) {
            int c = cbase + nt * 8;
            float2 v0 = { acc[mt][nt][0] + bv[nt][0], acc[mt][nt][1] + bv[nt][1] };
            float2 v1 = { acc[mt][nt][2] + bv[nt][0], acc[mt][nt][3] + bv[nt][1] };
            *(float2*)&C[(size_t)r0 * GN + c]       = v0;
            *(float2*)&C[(size_t)(r0 + 8) * GN + c] = v1;
        }
    }
}

// ---------------------------------------------------------------------------
// Mask dtype detection + expansion
// ---------------------------------------------------------------------------
__global__ void detect_mask_kernel(const unsigned* __restrict__ qm,
                                   const unsigned* __restrict__ km, int nints)
{
    __shared__ int s_i, s_f;
    for (int b = 0; b < 2; b++) {
        if (threadIdx.x == 0) { s_i = 1; s_f = 1; }
        __syncthreads();
        const unsigned* p = b ? km : qm;
        int li = 1, lf = 1;
        for (int i = threadIdx.x; i < nints; i += blockDim.x) {
            unsigned v = p[i];
            if (v > 1u) li = 0;
            if (v != 0u && v != 0x3f800000u) lf = 0;
        }
        if (!li) atomicAnd(&s_i, 0);
        if (!lf) atomicAnd(&s_f, 0);
        __syncthreads();
        if (threadIdx.x == 0)
            g_mask_mode[b] = s_i ? 1 : (s_f ? 2 : 0);
        __syncthreads();
    }
}

__global__ void expand_mask_kernel(const void* __restrict__ src,
                                   float* __restrict__ dst, int n, int which)
{
    int mode = g_mask_mode[which];
    int i = blockIdx.x * blockDim.x + threadIdx.x;
    if (i >= n) return;
    bool m;
    if (mode == 1)      m = ((const int*)src)[i] != 0;
    else if (mode == 2) m = ((const float*)src)[i] != 0.f;
    else                m = ((const unsigned char*)src)[i] != 0;
    dst[i] = m ? 1.f : 0.f;
}

// ---------------------------------------------------------------------------
// 4D RoPE
// ---------------------------------------------------------------------------
__global__ void rope_kernel(float* __restrict__ X, const float* __restrict__ coords,
                            const float* __restrict__ f0, const float* __restrict__ f1,
                            const float* __restrict__ f2)
{
    __shared__ float cs[32], sn[32];
    const int tok = blockIdx.x;
    const int tid = threadIdx.x;

    if (tid < 32) {
        float coord, fr;
        if (tid < 12)      { coord = coords[tok * 3 + 0]; fr = f0[tid]; }
        else if (tid < 22) { coord = coords[tok * 3 + 1]; fr = f1[tid - 12]; }
        else               { coord = coords[tok * 3 + 2]; fr = f2[tid - 22]; }
        float arg = 1.5707963267948966f * coord * fr;
        float s, c;
        sincosf(arg, &s, &c);
        sn[tid] = s; cs[tid] = c;
    }
    __syncthreads();

    float* xp = X + (size_t)tok * D_;
    for (int p = tid; p < H_ * 32; p += blockDim.x) {
        int h = p >> 5, j = p & 31;
        int idx = h * 64 + j * 2;
        float x0 = xp[idx], x1 = xp[idx + 1];
        float c = cs[j], s = sn[j];
        xp[idx]     = x0 * c - x1 * s;
        xp[idx + 1] = x1 * c + x0 * s;
    }
}

// ---------------------------------------------------------------------------
// HMMA flash attention: 64 q-rows per CTA, 4 warps (16 rows each),
// 3-pass hi/lo split for QK^T and PV, precomputed fused bias E.
// smem: K hi/lo (2x9216B), V^T hi/lo (2x9216B), E tile (17408B) = 54272B
// ---------------------------------------------------------------------------
#define ATT_SMEM 54272

__global__ void __launch_bounds__(128)
attn_mma(const __nv_bfloat16* __restrict__ Qh, const __nv_bfloat16* __restrict__ Ql,
         const __nv_bfloat16* __restrict__ Kh, const __nv_bfloat16* __restrict__ Kl,
         const __nv_bfloat16* __restrict__ Vth, const __nv_bfloat16* __restrict__ Vtl,
         const float* __restrict__ E, const float* __restrict__ alpha,
         float* __restrict__ Y)
{
    extern __shared__ char sm[];
    uint32_t* sKh = (uint32_t*)sm;              // 64 rows x 36 u32 (144B stride)
    uint32_t* sKl = (uint32_t*)(sm + 9216);
    uint32_t* sVh = (uint32_t*)(sm + 18432);
    uint32_t* sVl = (uint32_t*)(sm + 27648);
    float*    sE  = (float*)(sm + 36864);       // 64 rows x 68 f32

    const int tid = threadIdx.x;
    const int w = tid >> 5, lane = tid & 31;
    const int c = lane & 3, rg = lane >> 2;
    const int qb = blockIdx.x, fh = blockIdx.y;
    const int f = fh >> 4, h = fh & 15;
    const int tok0 = f * NQ_;
    const int q0 = qb * 64;
    const float alph = alpha[h];
    const int rl = 16 * w + rg;                 // local q row (low of pair)

    // stage Q hi/lo through smem, then to A fragments (resident for all tiles)
    for (int i = tid; i < 512; i += 128) {
        int row = i >> 3, c16 = i & 7;
        size_t go = (size_t)(tok0 + q0 + row) * D_ + h * 64 + c16 * 8;
        *(uint4*)(sKh + row * 36 + c16 * 4) = *(const uint4*)(Qh + go);
        *(uint4*)(sKl + row * 36 + c16 * 4) = *(const uint4*)(Ql + go);
    }
    __syncthreads();
    uint32_t qhF[4][4], qlF[4][4];
    #pragma unroll
    for (int s = 0; s < 4; s++) {
        qhF[s][0] = sKh[rl * 36 + 8 * s + c];
        qhF[s][1] = sKh[(rl + 8) * 36 + 8 * s + c];
        qhF[s][2] = sKh[rl * 36 + 8 * s + c + 4];
        qhF[s][3] = sKh[(rl + 8) * 36 + 8 * s + c + 4];
        qlF[s][0] = sKl[rl * 36 + 8 * s + c];
        qlF[s][1] = sKl[(rl + 8) * 36 + 8 * s + c];
        qlF[s][2] = sKl[rl * 36 + 8 * s + c + 4];
        qlF[s][3] = sKl[(rl + 8) * 36 + 8 * s + c + 4];
    }
    __syncthreads();

    float o[8][4];
    #pragma unroll
    for (int n = 0; n < 8; n++)
        #pragma unroll
        for (int r = 0; r < 4; r++) o[n][r] = 0.f;
    float m0r = -3.0e38f, m1r = -3.0e38f, l0r = 0.f, l1r = 0.f;

    for (int kt = 0; kt < 9; kt++) {
        const int k0 = kt * 64;
        // cooperative tile loads
        for (int i = tid; i < 512; i += 128) {
            int row = i >> 3, c16 = i & 7;
            size_t go = (size_t)(tok0 + k0 + row) * D_ + h * 64 + c16 * 8;
            *(uint4*)(sKh + row * 36 + c16 * 4) = *(const uint4*)(Kh + go);
            *(uint4*)(sKl + row * 36 + c16 * 4) = *(const uint4*)(Kl + go);
            size_t vo = (size_t)fh * (64 * NK_) + (size_t)row * NK_ + k0 + c16 * 8;
            *(uint4*)(sVh + row * 36 + c16 * 4) = *(const uint4*)(Vth + vo);
            *(uint4*)(sVl + row * 36 + c16 * 4) = *(const uint4*)(Vtl + vo);
        }
        for (int i = tid; i < 1024; i += 128) {
            int row = i >> 4, c4 = i & 15;
            *(float4*)(sE + row * 68 + c4 * 4) =
                *(const float4*)(E + (size_t)(tok0 + q0 + row) * NK_ + k0 + c4 * 4);
        }
        __syncthreads();

        // S = Q K^T (3-pass)
        float s[8][4];
        #pragma unroll
        for (int n = 0; n < 8; n++)
            #pragma unroll
            for (int r = 0; r < 4; r++) s[n][r] = 0.f;
        #pragma unroll
        for (int st = 0; st < 4; st++) {
            #pragma unroll
            for (int n = 0; n < 8; n++) {
                int bi = (8 * n + rg) * 36 + 8 * st + c;
                uint32_t bh[2] = { sKh[bi], sKh[bi + 4] };
                uint32_t bl[2] = { sKl[bi], sKl[bi + 4] };
                mma_bf16(s[n], qhF[st], bh);
                mma_bf16(s[n], qlF[st], bh);
                mma_bf16(s[n], qhF[st], bl);
            }
        }

        // fused bias + online softmax
        float mn0 = m0r, mn1 = m1r;
        #pragma unroll
        for (int n = 0; n < 8; n++) {
            float2 e0 = *(float2*)(sE + rl * 68 + 8 * n + 2 * c);
            float2 e1 = *(float2*)(sE + (rl + 8) * 68 + 8 * n + 2 * c);
            s[n][0] = (e0.x < 0.f) ? NEGBIG : fmaf(s[n][0], 0.125f, alph * e0.x);
            s[n][1] = (e0.y < 0.f) ? NEGBIG : fmaf(s[n][1], 0.125f, alph * e0.y);
            s[n][2] = (e1.x < 0.f) ? NEGBIG : fmaf(s[n][2], 0.125f, alph * e1.x);
            s[n][3] = (e1.y < 0.f) ? NEGBIG : fmaf(s[n][3], 0.125f, alph * e1.y);
            mn0 = fmaxf(mn0, fmaxf(s[n][0], s[n][1]));
            mn1 = fmaxf(mn1, fmaxf(s[n][2], s[n][3]));
        }
        mn0 = fmaxf(mn0, __shfl_xor_sync(0xffffffffu, mn0, 1));
        mn0 = fmaxf(mn0, __shfl_xor_sync(0xffffffffu, mn0, 2));
        mn1 = fmaxf(mn1, __shfl_xor_sync(0xffffffffu, mn1, 1));
        mn1 = fmaxf(mn1, __shfl_xor_sync(0xffffffffu, mn1, 2));
        float f0 = ex2((m0r - mn0) * LOG2E);
        float f1 = ex2((m1r - mn1) * LOG2E);
        m0r = mn0; m1r = mn1;

        float rs0 = 0.f, rs1 = 0.f;
        uint32_t phL[8], phH[8], plL[8], plH[8];
        #pragma unroll
        for (int n = 0; n < 8; n++) {
            float p0 = ex2((s[n][0] - mn0) * LOG2E);
            float p1 = ex2((s[n][1] - mn0) * LOG2E);
            float p2 = ex2((s[n][2] - mn1) * LOG2E);
            float p3 = ex2((s[n][3] - mn1) * LOG2E);
            rs0 += p0 + p1;
            rs1 += p2 + p3;
            o[n][0] *= f0; o[n][1] *= f0; o[n][2] *= f1; o[n][3] *= f1;
            __nv_bfloat162 bL = __float22bfloat162_rn(make_float2(p0, p1));
            phL[n] = *(uint32_t*)&bL;
            __nv_bfloat162 rL = __float22bfloat162_rn(make_float2(
                p0 - __bfloat162float(bL.x), p1 - __bfloat162float(bL.y)));
            plL[n] = *(uint32_t*)&rL;
            __nv_bfloat162 bH = __float22bfloat162_rn(make_float2(p2, p3));
            phH[n] = *(uint32_t*)&bH;
            __nv_bfloat162 rH = __float22bfloat162_rn(make_float2(
                p2 - __bfloat162float(bH.x), p3 - __bfloat162float(bH.y)));
            plH[n] = *(uint32_t*)&rH;
        }
        rs0 += __shfl_xor_sync(0xffffffffu, rs0, 1);
        rs0 += __shfl_xor_sync(0xffffffffu, rs0, 2);
        rs1 += __shfl_xor_sync(0xffffffffu, rs1, 1);
        rs1 += __shfl_xor_sync(0xffffffffu, rs1, 2);
        l0r = l0r * f0 + rs0;
        l1r = l1r * f1 + rs1;

        // O += P V (3-pass); P fragments repacked from S accumulators
        #pragma unroll
        for (int st = 0; st < 4; st++) {
            uint32_t ah[4] = { phL[2 * st], phH[2 * st], phL[2 * st + 1], phH[2 * st + 1] };
            uint32_t al[4] = { plL[2 * st], plH[2 * st], plL[2 * st + 1], plH[2 * st + 1] };
            #pragma unroll
            for (int n = 0; n < 8; n++) {
                int bi = (8 * n + rg) * 36 + 8 * st + c;
                uint32_t vh[2] = { sVh[bi], sVh[bi + 4] };
                uint32_t vl[2] = { sVl[bi], sVl[bi + 4] };
                mma_bf16(o[n], ah, vh);
                mma_bf16(o[n], al, vh);
                mma_bf16(o[n], ah, vl);
            }
        }
        __syncthreads();
    }

    // epilogue: Y[tok, h*64+d] = O / l
    float i0 = 1.f / l0r, i1 = 1.f / l1r;
    #pragma unroll
    for (int n = 0; n < 8; n++) {
        size_t r0 = (size_t)(tok0 + q0 + rl) * D_ + h * 64 + 8 * n + 2 * c;
        size_t r1 = (size_t)(tok0 + q0 + rl + 8) * D_ + h * 64 + 8 * n + 2 * c;
        float2 w0 = { o[n][0] * i0, o[n][1] * i0 };
        float2 w1 = { o[n][2] * i1, o[n][3] * i1 };
        *(float2*)(Y + r0) = w0;
        *(float2*)(Y + r1) = w1;
    }
}

// ---------------------------------------------------------------------------
extern "C" void kernel_launch(void* const* d_in, const int* in_sizes, int n_in,
                              void* d_out, int out_size)
{
    (void)in_sizes; (void)n_in; (void)out_size;

    const float*   q_tokens  = (const float*)d_in[0];
    const float*   kv_tokens = (const float*)d_in[1];
    const float*   coords_q  = (const float*)d_in[2];
    const float*   coords_k  = (const float*)d_in[3];
    const void*    q_pad     = d_in[4];
    const void*    kv_pad    = d_in[5];
    const float*   Wq = (const float*)d_in[6];
    const float*   bq = (const float*)d_in[7];
    const float*   Wk = (const float*)d_in[8];
    const float*   bk = (const float*)d_in[9];
    const float*   Wv = (const float*)d_in[10];
    const float*   bv = (const float*)d_in[11];
    const float*   Wo = (const float*)d_in[12];
    const float*   bo = (const float*)d_in[13];
    const float*   alpha = (const float*)d_in[14];
    const float*   f0 = (const float*)d_in[15];
    const float*   f1 = (const float*)d_in[16];
    const float*   f2 = (const float*)d_in[17];
    float* out = (float*)d_out;

    float *Qb, *Kb, *Vb, *Yb, *qmB, *kmB, *Eb;
    cudaGetSymbolAddress((void**)&Qb, g_Q);
    cudaGetSymbolAddress((void**)&Kb, g_K);
    cudaGetSymbolAddress((void**)&Vb, g_V);
    cudaGetSymbolAddress((void**)&Yb, g_Y);
    cudaGetSymbolAddress((void**)&qmB, g_qm);
    cudaGetSymbolAddress((void**)&kmB, g_km);
    cudaGetSymbolAddress((void**)&Eb, g_E);

    __nv_bfloat16 *qhi, *qlo, *kvhi, *kvlo, *yhi, *ylo;
    __nv_bfloat16 *Wqhi, *Wqlo, *Wkhi, *Wklo, *Wvhi, *Wvlo, *Wohi, *Wolo;
    __nv_bfloat16 *aQh, *aQl, *aKh, *aKl, *vth, *vtl;
    cudaGetSymbolAddress((void**)&qhi,  g_qhi);  cudaGetSymbolAddress((void**)&qlo,  g_qlo);
    cudaGetSymbolAddress((void**)&kvhi, g_kvhi); cudaGetSymbolAddress((void**)&kvlo, g_kvlo);
    cudaGetSymbolAddress((void**)&yhi,  g_yhi);  cudaGetSymbolAddress((void**)&ylo,  g_ylo);
    cudaGetSymbolAddress((void**)&Wqhi, g_Wqhi); cudaGetSymbolAddress((void**)&Wqlo, g_Wqlo);
    cudaGetSymbolAddress((void**)&Wkhi, g_Wkhi); cudaGetSymbolAddress((void**)&Wklo, g_Wklo);
    cudaGetSymbolAddress((void**)&Wvhi, g_Wvhi); cudaGetSymbolAddress((void**)&Wvlo, g_Wvlo);
    cudaGetSymbolAddress((void**)&Wohi, g_Wohi); cudaGetSymbolAddress((void**)&Wolo, g_Wolo);
    cudaGetSymbolAddress((void**)&aQh, g_aQh);   cudaGetSymbolAddress((void**)&aQl, g_aQl);
    cudaGetSymbolAddress((void**)&aKh, g_aKh);   cudaGetSymbolAddress((void**)&aKl, g_aKl);
    cudaGetSymbolAddress((void**)&vth, g_vth);   cudaGetSymbolAddress((void**)&vtl, g_vtl);

    const int gemm_smem = 2 * GBUF;
    cudaFuncSetAttribute(gemm_mma, cudaFuncAttributeMaxDynamicSharedMemorySize,
                         gemm_smem);
    cudaFuncSetAttribute(attn_mma, cudaFuncAttributeMaxDynamicSharedMemorySize,
                         ATT_SMEM);

    // masks + fused bias (head-independent, shared by 16 heads)
    detect_mask_kernel<<<1, 256>>>((const unsigned*)q_pad, (const unsigned*)kv_pad,
                                   TOK / 4);
    expand_mask_kernel<<<(TOK + 255) / 256, 256>>>(q_pad,  qmB, TOK, 0);
    expand_mask_kernel<<<(TOK + 255) / 256, 256>>>(kv_pad, kmB, TOK, 1);
    bias_kernel<<<dim3(NQ_, 8), NK_>>>(coords_q, coords_k, qmB, kmB, Eb);

    // bf16 hi/lo splits for projections
    const int ntok4 = TOK * D_ / 4, nw4 = D_ * D_ / 4;
    split_bf16_kernel<<<(ntok4 + 255) / 256, 256>>>(q_tokens,  qhi,  qlo,  ntok4);
    split_bf16_kernel<<<(ntok4 + 255) / 256, 256>>>(kv_tokens, kvhi, kvlo, ntok4);
    split_bf16_kernel<<<(nw4 + 255) / 256, 256>>>(Wq, Wqhi, Wqlo, nw4);
    split_bf16_kernel<<<(nw4 + 255) / 256, 256>>>(Wk, Wkhi, Wklo, nw4);
    split_bf16_kernel<<<(nw4 + 255) / 256, 256>>>(Wv, Wvhi, Wvlo, nw4);
    split_bf16_kernel<<<(nw4 + 255) / 256, 256>>>(Wo, Wohi, Wolo, nw4);

    dim3 gg(GN / 128, TOK / 128);
    gemm_mma<<<gg, 256, gemm_smem>>>(qhi,  qlo,  Wqhi, Wqlo, bq, Qb);
    gemm_mma<<<gg, 256, gemm_smem>>>(kvhi, kvlo, Wkhi, Wklo, bk, Kb);
    gemm_mma<<<gg, 256, gemm_smem>>>(kvhi, kvlo, Wvhi, Wvlo, bv, Vb);

    rope_kernel<<<TOK, 128>>>(Qb, coords_q, f0, f1, f2);
    rope_kernel<<<TOK, 128>>>(Kb, coords_k, f0, f1, f2);

    // attention operand prep: split Q/K, transpose+split V
    split_bf16_kernel<<<(ntok4 + 255) / 256, 256>>>(Qb, aQh, aQl, ntok4);
    split_bf16_kernel<<<(ntok4 + 255) / 256, 256>>>(Kb, aKh, aKl, ntok4);
    vtsplit_kernel<<<dim3(NK_ / 32, D_ / 32, 8), 256>>>(Vb, vth, vtl);

    attn_mma<<<dim3(9, 128), 128, ATT_SMEM>>>(aQh, aQl, aKh, aKl, vth, vtl,
                                              Eb, alpha, Yb);

    split_bf16_kernel<<<(ntok4 + 255) / 256, 256>>>(Yb, yhi, ylo, ntok4);
    gemm_mma<<<gg, 256, gemm_smem>>>(yhi, ylo, Wohi, Wolo, bo, out);
}

// round 6
// speedup vs baseline: 2.1513x; 1.1079x over previous
#include <cuda_runtime.h>
#include <cuda_bf16.h>
#include <cstdint>
#include <cstddef>
#include <math.h>

// Problem constants
#define B_   2
#define T_   4
#define NQ_  576
#define NK_  576
#define D_   1024
#define H_   16
#define DH_  64
#define TOK  (B_*T_*NQ_)
#define NEGBIG (-1.7014118e38f)
#define LOG2E 1.4426950408889634f

#define GK 1024
#define GN 1024

// Scratch (device globals; no dynamic allocation allowed)
__device__ float g_Q[TOK * D_];
__device__ float g_K[TOK * D_];
__device__ float g_V[TOK * D_];
__device__ float g_qm[TOK];
__device__ float g_km[TOK];
__device__ int   g_mask_mode[2];
__device__ float g_E[8 * NQ_ * NK_];          // fused bias: prior or -3e38

// bf16 hi/lo split operands
__device__ __nv_bfloat16 g_qhi[TOK * D_],  g_qlo[TOK * D_];
__device__ __nv_bfloat16 g_kvhi[TOK * D_], g_kvlo[TOK * D_];
__device__ __nv_bfloat16 g_yhi[TOK * D_],  g_ylo[TOK * D_];
__device__ __nv_bfloat16 g_Wqhi[D_ * D_],  g_Wqlo[D_ * D_];
__device__ __nv_bfloat16 g_Wkhi[D_ * D_],  g_Wklo[D_ * D_];
__device__ __nv_bfloat16 g_Wvhi[D_ * D_],  g_Wvlo[D_ * D_];
__device__ __nv_bfloat16 g_Wohi[D_ * D_],  g_Wolo[D_ * D_];

// attention operands (post-rope splits)
__device__ __nv_bfloat16 g_aQh[TOK * D_], g_aQl[TOK * D_];
__device__ __nv_bfloat16 g_aKh[TOK * D_], g_aKl[TOK * D_];
__device__ __nv_bfloat16 g_vth[128 * 64 * NK_], g_vtl[128 * 64 * NK_];

// ---------------------------------------------------------------------------
// Family-portable PTX helpers
// ---------------------------------------------------------------------------
__device__ __forceinline__ uint32_t smem_u32(const void* p) {
    uint32_t a;
    asm("{ .reg .u64 t; cvta.to.shared.u64 t, %1; cvt.u32.u64 %0, t; }"
        : "=r"(a) : "l"(p));
    return a;
}
__device__ __forceinline__ void cp16(uint32_t s, const void* g) {
    asm volatile("cp.async.cg.shared.global [%0], [%1], 16;"
                 :: "r"(s), "l"(g) : "memory");
}
__device__ __forceinline__ void cp_commit() {
    asm volatile("cp.async.commit_group;" ::: "memory");
}
__device__ __forceinline__ void cp_wait1() {
    asm volatile("cp.async.wait_group 1;" ::: "memory");
}
__device__ __forceinline__ void cp_wait0() {
    asm volatile("cp.async.wait_group 0;" ::: "memory");
}
__device__ __forceinline__ void ldm_x4(uint32_t* r, uint32_t addr) {
    asm volatile("ldmatrix.sync.aligned.m8n8.x4.shared.b16 {%0,%1,%2,%3}, [%4];"
                 : "=r"(r[0]), "=r"(r[1]), "=r"(r[2]), "=r"(r[3]) : "r"(addr));
}
__device__ __forceinline__ void mma_bf16(float* d, const uint32_t* a, const uint32_t* b) {
    asm volatile(
        "mma.sync.aligned.m16n8k16.row.col.f32.bf16.bf16.f32 "
        "{%0,%1,%2,%3}, {%4,%5,%6,%7}, {%8,%9}, {%0,%1,%2,%3};"
        : "+f"(d[0]), "+f"(d[1]), "+f"(d[2]), "+f"(d[3])
        : "r"(a[0]), "r"(a[1]), "r"(a[2]), "r"(a[3]), "r"(b[0]), "r"(b[1]));
}
__device__ __forceinline__ float ex2(float x) {
    float y;
    asm("ex2.approx.f32 %0, %1;" : "=f"(y) : "f"(x));
    return y;
}

// ---------------------------------------------------------------------------
// fp32 -> bf16 hi/lo split (vectorized by 4)
// ---------------------------------------------------------------------------
__global__ void split_bf16_kernel(const float* __restrict__ x,
                                  __nv_bfloat16* __restrict__ hi,
                                  __nv_bfloat16* __restrict__ lo, int n4)
{
    int i = blockIdx.x * blockDim.x + threadIdx.x;
    if (i >= n4) return;
    float4 v = ((const float4*)x)[i];
    __nv_bfloat16 h0 = __float2bfloat16(v.x);
    __nv_bfloat16 h1 = __float2bfloat16(v.y);
    __nv_bfloat16 h2 = __float2bfloat16(v.z);
    __nv_bfloat16 h3 = __float2bfloat16(v.w);
    __nv_bfloat16 l0 = __float2bfloat16(v.x - __bfloat162float(h0));
    __nv_bfloat16 l1 = __float2bfloat16(v.y - __bfloat162float(h1));
    __nv_bfloat16 l2 = __float2bfloat16(v.z - __bfloat162float(h2));
    __nv_bfloat16 l3 = __float2bfloat16(v.w - __bfloat162float(h3));
    ((__nv_bfloat162*)hi)[2*i]   = __nv_bfloat162(h0, h1);
    ((__nv_bfloat162*)hi)[2*i+1] = __nv_bfloat162(h2, h3);
    ((__nv_bfloat162*)lo)[2*i]   = __nv_bfloat162(l0, l1);
    ((__nv_bfloat162*)lo)[2*i+1] = __nv_bfloat162(l2, l3);
}

// ---------------------------------------------------------------------------
// V transpose + split
// ---------------------------------------------------------------------------
__global__ void vtsplit_kernel(const float* __restrict__ V,
                               __nv_bfloat16* __restrict__ vh,
                               __nv_bfloat16* __restrict__ vl)
{
    __shared__ float t[32][33];
    const int k0 = blockIdx.x * 32, d0 = blockIdx.y * 32, f = blockIdx.z;
    const int tx = threadIdx.x & 31, ty = threadIdx.x >> 5;
    #pragma unroll
    for (int i = 0; i < 4; i++) {
        int key = k0 + ty + i * 8;
        t[ty + i * 8][tx] = V[(size_t)(f * NQ_ + key) * D_ + d0 + tx];
    }
    __syncthreads();
    #pragma unroll
    for (int i = 0; i < 4; i++) {
        int dd = ty + i * 8;
        int d = d0 + dd, h = d >> 6, dl = d & 63;
        float v = t[tx][dd];
        __nv_bfloat16 hi = __float2bfloat16(v);
        __nv_bfloat16 lo = __float2bfloat16(v - __bfloat162float(hi));
        size_t oi = ((size_t)(f * 16 + h) * 64 + dl) * NK_ + k0 + tx;
        vh[oi] = hi;
        vl[oi] = lo;
    }
}

// ---------------------------------------------------------------------------
// Fused bias precompute (head-independent)
// ---------------------------------------------------------------------------
__global__ void bias_kernel(const float* __restrict__ cq, const float* __restrict__ ck,
                            const float* __restrict__ qm, const float* __restrict__ km,
                            float* __restrict__ E)
{
    const int q = blockIdx.x, f = blockIdx.y, k = threadIdx.x;
    const int qi = f * NQ_ + q, ki = f * NK_ + k;
    float qy = cq[qi * 3 + 1], qx = cq[qi * 3 + 2];
    float dy = qy - ck[ki * 3 + 1];
    float dx = qx - ck[ki * 3 + 2];
    float dist = sqrtf(dy * dy + dx * dx);
    bool bad = (qm[qi] + km[ki] > 0.f) || (dist > 0.5f);
    E[(size_t)qi * NK_ + k] = bad ? -3.0e38f : __expf(-10.f * dist);
}

// ---------------------------------------------------------------------------
// HMMA GEMM: 3-pass bf16 split, 128x128 CTA tile, 4 warps (64x64 each),
// 3-stage cp.async pipeline, single __syncthreads per k-chunk.
// ---------------------------------------------------------------------------
#define TILE_B 10240            // 128 rows * 80 B
#define GBUF   (2 * TILE_B)     // A + B tiles per stage
#define NCH    96               // 3 passes * 32 k-chunks

__global__ void __launch_bounds__(128)
gemm_mma(const __nv_bfloat16* __restrict__ Ahi, const __nv_bfloat16* __restrict__ Alo,
         const __nv_bfloat16* __restrict__ Bhi, const __nv_bfloat16* __restrict__ Blo,
         const float* __restrict__ bias, float* __restrict__ C)
{
    extern __shared__ char dsm[];
    const uint32_t sbase = smem_u32(dsm);

    const int tid  = threadIdx.x;
    const int wid  = tid >> 5;
    const int lane = tid & 31;
    const int m0 = blockIdx.y * 128;
    const int n0 = blockIdx.x * 128;
    const int wm = (wid & 1) * 64;
    const int wn = (wid >> 1) * 64;

    float acc[4][8][4];
    #pragma unroll
    for (int mt = 0; mt < 4; mt++)
        #pragma unroll
        for (int nt = 0; nt < 8; nt++)
            #pragma unroll
            for (int r = 0; r < 4; r++) acc[mt][nt][r] = 0.f;

    // per-thread load slots: 1024 cp16 per chunk, 8 per thread
    int l_tl[8], l_row[8], l_c[8];
    #pragma unroll
    for (int j = 0; j < 8; j++) {
        int i = tid + j * 128;
        l_tl[j]  = i >> 9;
        l_row[j] = (i & 511) >> 2;
        l_c[j]   = i & 3;
    }

    auto issue_load = [&](int ch, int buf) {
        const int p = ch >> 5;
        const int k0 = (ch & 31) * 32;
        const __nv_bfloat16* As = (p == 1) ? Alo : Ahi;
        const __nv_bfloat16* Bs = (p == 2) ? Blo : Bhi;
        #pragma unroll
        for (int j = 0; j < 8; j++) {
            const __nv_bfloat16* g = l_tl[j]
                ? Bs + (size_t)(n0 + l_row[j]) * GK + k0 + l_c[j] * 8
                : As + (size_t)(m0 + l_row[j]) * GK + k0 + l_c[j] * 8;
            uint32_t s = sbase + buf * GBUF + l_tl[j] * TILE_B
                       + l_row[j] * 80 + l_c[j] * 16;
            cp16(s, g);
        }
        cp_commit();
    };

    issue_load(0, 0);
    issue_load(1, 1);

    for (int ch = 0; ch < NCH; ch++) {
        if (ch == NCH - 1) cp_wait0(); else cp_wait1();
        __syncthreads();
        if (ch + 2 < NCH) issue_load(ch + 2, (ch + 2) % 3);

        const uint32_t abase = sbase + (ch % 3) * GBUF;
        const uint32_t bbase = abase + TILE_B;

        #pragma unroll
        for (int ks = 0; ks < 2; ks++) {
            uint32_t a[4][4], b[8][2];
            #pragma unroll
            for (int mt = 0; mt < 4; mt++) {
                uint32_t addr = abase + (wm + mt * 16 + (lane & 15)) * 80
                              + (lane >> 4) * 16 + ks * 32;
                ldm_x4(a[mt], addr);
            }
            #pragma unroll
            for (int np = 0; np < 4; np++) {
                uint32_t addr = bbase
                    + (wn + np * 16 + (lane & 7) + ((lane >> 4) & 1) * 8) * 80
                    + ((lane >> 3) & 1) * 16 + ks * 32;
                uint32_t r[4];
                ldm_x4(r, addr);
                b[np * 2][0] = r[0];     b[np * 2][1] = r[1];
                b[np * 2 + 1][0] = r[2]; b[np * 2 + 1][1] = r[3];
            }
            #pragma unroll
            for (int mt = 0; mt < 4; mt++)
                #pragma unroll
                for (int nt = 0; nt < 8; nt++)
                    mma_bf16(acc[mt][nt], a[mt], b[nt]);
        }
    }

    // epilogue: +bias, write fp32
    const int cbase = n0 + wn + (lane & 3) * 2;
    float bv[8][2];
    #pragma unroll
    for (int nt = 0; nt < 8; nt++) {
        bv[nt][0] = bias[cbase + nt * 8];
        bv[nt][1] = bias[cbase + nt * 8 + 1];
    }
    #pragma unroll
    for (int mt = 0; mt < 4; mt++) {
        int r0 = m0 + wm + mt * 16 + (lane >> 2);
        #pragma unroll
        for (int nt = 0; nt < 8; nt++) {
            int c = cbase + nt * 8;
            float2 v0 = { acc[mt][nt][0] + bv[nt][0], acc[mt][nt][1] + bv[nt][1] };
            float2 v1 = { acc[mt][nt][2] + bv[nt][0], acc[mt][nt][3] + bv[nt][1] };
            *(float2*)&C[(size_t)r0 * GN + c]       = v0;
            *(float2*)&C[(size_t)(r0 + 8) * GN + c] = v1;
        }
    }
}

// ---------------------------------------------------------------------------
// Mask dtype detection + expansion
// ---------------------------------------------------------------------------
__global__ void detect_mask_kernel(const unsigned* __restrict__ qm,
                                   const unsigned* __restrict__ km, int nints)
{
    __shared__ int s_i, s_f;
    for (int b = 0; b < 2; b++) {
        if (threadIdx.x == 0) { s_i = 1; s_f = 1; }
        __syncthreads();
        const unsigned* p = b ? km : qm;
        int li = 1, lf = 1;
        for (int i = threadIdx.x; i < nints; i += blockDim.x) {
            unsigned v = p[i];
            if (v > 1u) li = 0;
            if (v != 0u && v != 0x3f800000u) lf = 0;
        }
        if (!li) atomicAnd(&s_i, 0);
        if (!lf) atomicAnd(&s_f, 0);
        __syncthreads();
        if (threadIdx.x == 0)
            g_mask_mode[b] = s_i ? 1 : (s_f ? 2 : 0);
        __syncthreads();
    }
}

__global__ void expand_mask_kernel(const void* __restrict__ src,
                                   float* __restrict__ dst, int n, int which)
{
    int mode = g_mask_mode[which];
    int i = blockIdx.x * blockDim.x + threadIdx.x;
    if (i >= n) return;
    bool m;
    if (mode == 1)      m = ((const int*)src)[i] != 0;
    else if (mode == 2) m = ((const float*)src)[i] != 0.f;
    else                m = ((const unsigned char*)src)[i] != 0;
    dst[i] = m ? 1.f : 0.f;
}

// ---------------------------------------------------------------------------
// 4D RoPE fused with bf16 hi/lo split (writes attention operands directly)
// ---------------------------------------------------------------------------
__global__ void rope_split_kernel(const float* __restrict__ X,
                                  const float* __restrict__ coords,
                                  const float* __restrict__ f0,
                                  const float* __restrict__ f1,
                                  const float* __restrict__ f2,
                                  __nv_bfloat16* __restrict__ hi,
                                  __nv_bfloat16* __restrict__ lo)
{
    __shared__ float cs[32], sn[32];
    const int tok = blockIdx.x;
    const int tid = threadIdx.x;

    if (tid < 32) {
        float coord, fr;
        if (tid < 12)      { coord = coords[tok * 3 + 0]; fr = f0[tid]; }
        else if (tid < 22) { coord = coords[tok * 3 + 1]; fr = f1[tid - 12]; }
        else               { coord = coords[tok * 3 + 2]; fr = f2[tid - 22]; }
        float arg = 1.5707963267948966f * coord * fr;
        float s, c;
        sincosf(arg, &s, &c);
        sn[tid] = s; cs[tid] = c;
    }
    __syncthreads();

    const float* xp = X + (size_t)tok * D_;
    __nv_bfloat162* hp = (__nv_bfloat162*)(hi + (size_t)tok * D_);
    __nv_bfloat162* lp = (__nv_bfloat162*)(lo + (size_t)tok * D_);
    for (int p = tid; p < H_ * 32; p += blockDim.x) {
        int h = p >> 5, j = p & 31;
        int idx = h * 64 + j * 2;
        float x0 = xp[idx], x1 = xp[idx + 1];
        float c = cs[j], s = sn[j];
        float y0 = x0 * c - x1 * s;
        float y1 = x1 * c + x0 * s;
        __nv_bfloat162 hv = __float22bfloat162_rn(make_float2(y0, y1));
        __nv_bfloat162 lv = __float22bfloat162_rn(make_float2(
            y0 - __bfloat162float(hv.x), y1 - __bfloat162float(hv.y)));
        hp[idx >> 1] = hv;
        lp[idx >> 1] = lv;
    }
}

// ---------------------------------------------------------------------------
// HMMA flash attention (as round 5) but epilogue writes bf16 hi/lo directly.
// ---------------------------------------------------------------------------
#define ATT_SMEM 54272

__global__ void __launch_bounds__(128)
attn_mma(const __nv_bfloat16* __restrict__ Qh, const __nv_bfloat16* __restrict__ Ql,
         const __nv_bfloat16* __restrict__ Kh, const __nv_bfloat16* __restrict__ Kl,
         const __nv_bfloat16* __restrict__ Vth, const __nv_bfloat16* __restrict__ Vtl,
         const float* __restrict__ E, const float* __restrict__ alpha,
         __nv_bfloat16* __restrict__ Yh, __nv_bfloat16* __restrict__ Yl)
{
    extern __shared__ char sm[];
    uint32_t* sKh = (uint32_t*)sm;
    uint32_t* sKl = (uint32_t*)(sm + 9216);
    uint32_t* sVh = (uint32_t*)(sm + 18432);
    uint32_t* sVl = (uint32_t*)(sm + 27648);
    float*    sE  = (float*)(sm + 36864);

    const int tid = threadIdx.x;
    const int w = tid >> 5, lane = tid & 31;
    const int c = lane & 3, rg = lane >> 2;
    const int qb = blockIdx.x, fh = blockIdx.y;
    const int f = fh >> 4, h = fh & 15;
    const int tok0 = f * NQ_;
    const int q0 = qb * 64;
    const float alph = alpha[h];
    const int rl = 16 * w + rg;

    for (int i = tid; i < 512; i += 128) {
        int row = i >> 3, c16 = i & 7;
        size_t go = (size_t)(tok0 + q0 + row) * D_ + h * 64 + c16 * 8;
        *(uint4*)(sKh + row * 36 + c16 * 4) = *(const uint4*)(Qh + go);
        *(uint4*)(sKl + row * 36 + c16 * 4) = *(const uint4*)(Ql + go);
    }
    __syncthreads();
    uint32_t qhF[4][4], qlF[4][4];
    #pragma unroll
    for (int s = 0; s < 4; s++) {
        qhF[s][0] = sKh[rl * 36 + 8 * s + c];
        qhF[s][1] = sKh[(rl + 8) * 36 + 8 * s + c];
        qhF[s][2] = sKh[rl * 36 + 8 * s + c + 4];
        qhF[s][3] = sKh[(rl + 8) * 36 + 8 * s + c + 4];
        qlF[s][0] = sKl[rl * 36 + 8 * s + c];
        qlF[s][1] = sKl[(rl + 8) * 36 + 8 * s + c];
        qlF[s][2] = sKl[rl * 36 + 8 * s + c + 4];
        qlF[s][3] = sKl[(rl + 8) * 36 + 8 * s + c + 4];
    }
    __syncthreads();

    float o[8][4];
    #pragma unroll
    for (int n = 0; n < 8; n++)
        #pragma unroll
        for (int r = 0; r < 4; r++) o[n][r] = 0.f;
    float m0r = -3.0e38f, m1r = -3.0e38f, l0r = 0.f, l1r = 0.f;

    for (int kt = 0; kt < 9; kt++) {
        const int k0 = kt * 64;
        for (int i = tid; i < 512; i += 128) {
            int row = i >> 3, c16 = i & 7;
            size_t go = (size_t)(tok0 + k0 + row) * D_ + h * 64 + c16 * 8;
            *(uint4*)(sKh + row * 36 + c16 * 4) = *(const uint4*)(Kh + go);
            *(uint4*)(sKl + row * 36 + c16 * 4) = *(const uint4*)(Kl + go);
            size_t vo = (size_t)fh * (64 * NK_) + (size_t)row * NK_ + k0 + c16 * 8;
            *(uint4*)(sVh + row * 36 + c16 * 4) = *(const uint4*)(Vth + vo);
            *(uint4*)(sVl + row * 36 + c16 * 4) = *(const uint4*)(Vtl + vo);
        }
        for (int i = tid; i < 1024; i += 128) {
            int row = i >> 4, c4 = i & 15;
            *(float4*)(sE + row * 68 + c4 * 4) =
                *(const float4*)(E + (size_t)(tok0 + q0 + row) * NK_ + k0 + c4 * 4);
        }
        __syncthreads();

        float s[8][4];
        #pragma unroll
        for (int n = 0; n < 8; n++)
            #pragma unroll
            for (int r = 0; r < 4; r++) s[n][r] = 0.f;
        #pragma unroll
        for (int st = 0; st < 4; st++) {
            #pragma unroll
            for (int n = 0; n < 8; n++) {
                int bi = (8 * n + rg) * 36 + 8 * st + c;
                uint32_t bh[2] = { sKh[bi], sKh[bi + 4] };
                uint32_t bl[2] = { sKl[bi], sKl[bi + 4] };
                mma_bf16(s[n], qhF[st], bh);
                mma_bf16(s[n], qlF[st], bh);
                mma_bf16(s[n], qhF[st], bl);
            }
        }

        float mn0 = m0r, mn1 = m1r;
        #pragma unroll
        for (int n = 0; n < 8; n++) {
            float2 e0 = *(float2*)(sE + rl * 68 + 8 * n + 2 * c);
            float2 e1 = *(float2*)(sE + (rl + 8) * 68 + 8 * n + 2 * c);
            s[n][0] = (e0.x < 0.f) ? NEGBIG : fmaf(s[n][0], 0.125f, alph * e0.x);
            s[n][1] = (e0.y < 0.f) ? NEGBIG : fmaf(s[n][1], 0.125f, alph * e0.y);
            s[n][2] = (e1.x < 0.f) ? NEGBIG : fmaf(s[n][2], 0.125f, alph * e1.x);
            s[n][3] = (e1.y < 0.f) ? NEGBIG : fmaf(s[n][3], 0.125f, alph * e1.y);
            mn0 = fmaxf(mn0, fmaxf(s[n][0], s[n][1]));
            mn1 = fmaxf(mn1, fmaxf(s[n][2], s[n][3]));
        }
        mn0 = fmaxf(mn0, __shfl_xor_sync(0xffffffffu, mn0, 1));
        mn0 = fmaxf(mn0, __shfl_xor_sync(0xffffffffu, mn0, 2));
        mn1 = fmaxf(mn1, __shfl_xor_sync(0xffffffffu, mn1, 1));
        mn1 = fmaxf(mn1, __shfl_xor_sync(0xffffffffu, mn1, 2));
        float f0 = ex2((m0r - mn0) * LOG2E);
        float f1 = ex2((m1r - mn1) * LOG2E);
        m0r = mn0; m1r = mn1;

        float rs0 = 0.f, rs1 = 0.f;
        uint32_t phL[8], phH[8], plL[8], plH[8];
        #pragma unroll
        for (int n = 0; n < 8; n++) {
            float p0 = ex2((s[n][0] - mn0) * LOG2E);
            float p1 = ex2((s[n][1] - mn0) * LOG2E);
            float p2 = ex2((s[n][2] - mn1) * LOG2E);
            float p3 = ex2((s[n][3] - mn1) * LOG2E);
            rs0 += p0 + p1;
            rs1 += p2 + p3;
            o[n][0] *= f0; o[n][1] *= f0; o[n][2] *= f1; o[n][3] *= f1;
            __nv_bfloat162 bL = __float22bfloat162_rn(make_float2(p0, p1));
            phL[n] = *(uint32_t*)&bL;
            __nv_bfloat162 rL = __float22bfloat162_rn(make_float2(
                p0 - __bfloat162float(bL.x), p1 - __bfloat162float(bL.y)));
            plL[n] = *(uint32_t*)&rL;
            __nv_bfloat162 bH = __float22bfloat162_rn(make_float2(p2, p3));
            phH[n] = *(uint32_t*)&bH;
            __nv_bfloat162 rH = __float22bfloat162_rn(make_float2(
                p2 - __bfloat162float(bH.x), p3 - __bfloat162float(bH.y)));
            plH[n] = *(uint32_t*)&rH;
        }
        rs0 += __shfl_xor_sync(0xffffffffu, rs0, 1);
        rs0 += __shfl_xor_sync(0xffffffffu, rs0, 2);
        rs1 += __shfl_xor_sync(0xffffffffu, rs1, 1);
        rs1 += __shfl_xor_sync(0xffffffffu, rs1, 2);
        l0r = l0r * f0 + rs0;
        l1r = l1r * f1 + rs1;

        #pragma unroll
        for (int st = 0; st < 4; st++) {
            uint32_t ah[4] = { phL[2 * st], phH[2 * st], phL[2 * st + 1], phH[2 * st + 1] };
            uint32_t al[4] = { plL[2 * st], plH[2 * st], plL[2 * st + 1], plH[2 * st + 1] };
            #pragma unroll
            for (int n = 0; n < 8; n++) {
                int bi = (8 * n + rg) * 36 + 8 * st + c;
                uint32_t vh[2] = { sVh[bi], sVh[bi + 4] };
                uint32_t vl[2] = { sVl[bi], sVl[bi + 4] };
                mma_bf16(o[n], ah, vh);
                mma_bf16(o[n], al, vh);
                mma_bf16(o[n], ah, vl);
            }
        }
        __syncthreads();
    }

    // epilogue: write hi/lo bf16 directly (feeds Wo GEMM)
    float i0 = 1.f / l0r, i1 = 1.f / l1r;
    #pragma unroll
    for (int n = 0; n < 8; n++) {
        size_t e0 = ((size_t)(tok0 + q0 + rl) * D_ + h * 64 + 8 * n + 2 * c) >> 1;
        size_t e1 = ((size_t)(tok0 + q0 + rl + 8) * D_ + h * 64 + 8 * n + 2 * c) >> 1;
        float2 w0 = { o[n][0] * i0, o[n][1] * i0 };
        float2 w1 = { o[n][2] * i1, o[n][3] * i1 };
        __nv_bfloat162 h0 = __float22bfloat162_rn(w0);
        __nv_bfloat162 l0v = __float22bfloat162_rn(make_float2(
            w0.x - __bfloat162float(h0.x), w0.y - __bfloat162float(h0.y)));
        __nv_bfloat162 h1 = __float22bfloat162_rn(w1);
        __nv_bfloat162 l1v = __float22bfloat162_rn(make_float2(
            w1.x - __bfloat162float(h1.x), w1.y - __bfloat162float(h1.y)));
        ((__nv_bfloat162*)Yh)[e0] = h0;
        ((__nv_bfloat162*)Yl)[e0] = l0v;
        ((__nv_bfloat162*)Yh)[e1] = h1;
        ((__nv_bfloat162*)Yl)[e1] = l1v;
    }
}

// ---------------------------------------------------------------------------
extern "C" void kernel_launch(void* const* d_in, const int* in_sizes, int n_in,
                              void* d_out, int out_size)
{
    (void)in_sizes; (void)n_in; (void)out_size;

    const float*   q_tokens  = (const float*)d_in[0];
    const float*   kv_tokens = (const float*)d_in[1];
    const float*   coords_q  = (const float*)d_in[2];
    const float*   coords_k  = (const float*)d_in[3];
    const void*    q_pad     = d_in[4];
    const void*    kv_pad    = d_in[5];
    const float*   Wq = (const float*)d_in[6];
    const float*   bq = (const float*)d_in[7];
    const float*   Wk = (const float*)d_in[8];
    const float*   bk = (const float*)d_in[9];
    const float*   Wv = (const float*)d_in[10];
    const float*   bv = (const float*)d_in[11];
    const float*   Wo = (const float*)d_in[12];
    const float*   bo = (const float*)d_in[13];
    const float*   alpha = (const float*)d_in[14];
    const float*   f0 = (const float*)d_in[15];
    const float*   f1 = (const float*)d_in[16];
    const float*   f2 = (const float*)d_in[17];
    float* out = (float*)d_out;

    float *Qb, *Kb, *Vb, *qmB, *kmB, *Eb;
    cudaGetSymbolAddress((void**)&Qb, g_Q);
    cudaGetSymbolAddress((void**)&Kb, g_K);
    cudaGetSymbolAddress((void**)&Vb, g_V);
    cudaGetSymbolAddress((void**)&qmB, g_qm);
    cudaGetSymbolAddress((void**)&kmB, g_km);
    cudaGetSymbolAddress((void**)&Eb, g_E);

    __nv_bfloat16 *qhi, *qlo, *kvhi, *kvlo, *yhi, *ylo;
    __nv_bfloat16 *Wqhi, *Wqlo, *Wkhi, *Wklo, *Wvhi, *Wvlo, *Wohi, *Wolo;
    __nv_bfloat16 *aQh, *aQl, *aKh, *aKl, *vth, *vtl;
    cudaGetSymbolAddress((void**)&qhi,  g_qhi);  cudaGetSymbolAddress((void**)&qlo,  g_qlo);
    cudaGetSymbolAddress((void**)&kvhi, g_kvhi); cudaGetSymbolAddress((void**)&kvlo, g_kvlo);
    cudaGetSymbolAddress((void**)&yhi,  g_yhi);  cudaGetSymbolAddress((void**)&ylo,  g_ylo);
    cudaGetSymbolAddress((void**)&Wqhi, g_Wqhi); cudaGetSymbolAddress((void**)&Wqlo, g_Wqlo);
    cudaGetSymbolAddress((void**)&Wkhi, g_Wkhi); cudaGetSymbolAddress((void**)&Wklo, g_Wklo);
    cudaGetSymbolAddress((void**)&Wvhi, g_Wvhi); cudaGetSymbolAddress((void**)&Wvlo, g_Wvlo);
    cudaGetSymbolAddress((void**)&Wohi, g_Wohi); cudaGetSymbolAddress((void**)&Wolo, g_Wolo);
    cudaGetSymbolAddress((void**)&aQh, g_aQh);   cudaGetSymbolAddress((void**)&aQl, g_aQl);
    cudaGetSymbolAddress((void**)&aKh, g_aKh);   cudaGetSymbolAddress((void**)&aKl, g_aKl);
    cudaGetSymbolAddress((void**)&vth, g_vth);   cudaGetSymbolAddress((void**)&vtl, g_vtl);

    const int gemm_smem = 3 * GBUF;  // 61440
    cudaFuncSetAttribute(gemm_mma, cudaFuncAttributeMaxDynamicSharedMemorySize,
                         gemm_smem);
    cudaFuncSetAttribute(attn_mma, cudaFuncAttributeMaxDynamicSharedMemorySize,
                         ATT_SMEM);

    // masks + fused bias
    detect_mask_kernel<<<1, 256>>>((const unsigned*)q_pad, (const unsigned*)kv_pad,
                                   TOK / 4);
    expand_mask_kernel<<<(TOK + 255) / 256, 256>>>(q_pad,  qmB, TOK, 0);
    expand_mask_kernel<<<(TOK + 255) / 256, 256>>>(kv_pad, kmB, TOK, 1);
    bias_kernel<<<dim3(NQ_, 8), NK_>>>(coords_q, coords_k, qmB, kmB, Eb);

    // bf16 hi/lo splits for projection inputs
    const int ntok4 = TOK * D_ / 4, nw4 = D_ * D_ / 4;
    split_bf16_kernel<<<(ntok4 + 255) / 256, 256>>>(q_tokens,  qhi,  qlo,  ntok4);
    split_bf16_kernel<<<(ntok4 + 255) / 256, 256>>>(kv_tokens, kvhi, kvlo, ntok4);
    split_bf16_kernel<<<(nw4 + 255) / 256, 256>>>(Wq, Wqhi, Wqlo, nw4);
    split_bf16_kernel<<<(nw4 + 255) / 256, 256>>>(Wk, Wkhi, Wklo, nw4);
    split_bf16_kernel<<<(nw4 + 255) / 256, 256>>>(Wv, Wvhi, Wvlo, nw4);
    split_bf16_kernel<<<(nw4 + 255) / 256, 256>>>(Wo, Wohi, Wolo, nw4);

    dim3 gg(GN / 128, TOK / 128);
    gemm_mma<<<gg, 128, gemm_smem>>>(qhi,  qlo,  Wqhi, Wqlo, bq, Qb);
    gemm_mma<<<gg, 128, gemm_smem>>>(kvhi, kvlo, Wkhi, Wklo, bk, Kb);
    gemm_mma<<<gg, 128, gemm_smem>>>(kvhi, kvlo, Wvhi, Wvlo, bv, Vb);

    // RoPE fused with attention-operand split
    rope_split_kernel<<<TOK, 128>>>(Qb, coords_q, f0, f1, f2, aQh, aQl);
    rope_split_kernel<<<TOK, 128>>>(Kb, coords_k, f0, f1, f2, aKh, aKl);
    vtsplit_kernel<<<dim3(NK_ / 32, D_ / 32, 8), 256>>>(Vb, vth, vtl);

    attn_mma<<<dim3(9, 128), 128, ATT_SMEM>>>(aQh, aQl, aKh, aKl, vth, vtl,
                                              Eb, alpha, yhi, ylo);

    gemm_mma<<<gg, 128, gemm_smem>>>(yhi, ylo, Wohi, Wolo, bo, out);
}

// round 7
// speedup vs baseline: 2.7895x; 1.2966x over previous
#include <cuda_runtime.h>
#include <cuda_bf16.h>
#include <cuda_fp16.h>
#include <cstdint>
#include <cstddef>
#include <math.h>

// Problem constants
#define B_   2
#define T_   4
#define NQ_  576
#define NK_  576
#define D_   1024
#define H_   16
#define DH_  64
#define TOK  (B_*T_*NQ_)
#define NEGBIG (-1.7014118e38f)
#define LOG2E 1.4426950408889634f

#define GK 1024
#define GN 1024

// Scratch (device globals; no dynamic allocation allowed)
__device__ float g_Q[TOK * D_];
__device__ float g_K[TOK * D_];
__device__ float g_V[TOK * D_];
__device__ float g_qm[TOK];
__device__ float g_km[TOK];
__device__ int   g_mask_mode[2];
__device__ float g_E[8 * NQ_ * NK_];

// fp16 hi/lo activations + single-rounded fp16 weights (GEMM path)
__device__ __half g_qhi[TOK * D_],  g_qlo[TOK * D_];
__device__ __half g_kvhi[TOK * D_], g_kvlo[TOK * D_];
__device__ __half g_yhi[TOK * D_],  g_ylo[TOK * D_];
__device__ __half g_Wqh[D_ * D_], g_Wkh[D_ * D_], g_Wvh[D_ * D_], g_Woh[D_ * D_];

// attention operands (bf16 hi/lo, post-rope)
__device__ __nv_bfloat16 g_aQh[TOK * D_], g_aQl[TOK * D_];
__device__ __nv_bfloat16 g_aKh[TOK * D_], g_aKl[TOK * D_];
__device__ __nv_bfloat16 g_vth[128 * 64 * NK_], g_vtl[128 * 64 * NK_];

// ---------------------------------------------------------------------------
// Family-portable PTX helpers
// ---------------------------------------------------------------------------
__device__ __forceinline__ uint32_t smem_u32(const void* p) {
    uint32_t a;
    asm("{ .reg .u64 t; cvta.to.shared.u64 t, %1; cvt.u32.u64 %0, t; }"
        : "=r"(a) : "l"(p));
    return a;
}
__device__ __forceinline__ void cp16(uint32_t s, const void* g) {
    asm volatile("cp.async.cg.shared.global [%0], [%1], 16;"
                 :: "r"(s), "l"(g) : "memory");
}
__device__ __forceinline__ void cp_commit() {
    asm volatile("cp.async.commit_group;" ::: "memory");
}
__device__ __forceinline__ void cp_wait1() {
    asm volatile("cp.async.wait_group 1;" ::: "memory");
}
__device__ __forceinline__ void cp_wait0() {
    asm volatile("cp.async.wait_group 0;" ::: "memory");
}
__device__ __forceinline__ void ldm_x4(uint32_t* r, uint32_t addr) {
    asm volatile("ldmatrix.sync.aligned.m8n8.x4.shared.b16 {%0,%1,%2,%3}, [%4];"
                 : "=r"(r[0]), "=r"(r[1]), "=r"(r[2]), "=r"(r[3]) : "r"(addr));
}
__device__ __forceinline__ void mma_f16(float* d, const uint32_t* a, const uint32_t* b) {
    asm volatile(
        "mma.sync.aligned.m16n8k16.row.col.f32.f16.f16.f32 "
        "{%0,%1,%2,%3}, {%4,%5,%6,%7}, {%8,%9}, {%0,%1,%2,%3};"
        : "+f"(d[0]), "+f"(d[1]), "+f"(d[2]), "+f"(d[3])
        : "r"(a[0]), "r"(a[1]), "r"(a[2]), "r"(a[3]), "r"(b[0]), "r"(b[1]));
}
__device__ __forceinline__ void mma_bf16(float* d, const uint32_t* a, const uint32_t* b) {
    asm volatile(
        "mma.sync.aligned.m16n8k16.row.col.f32.bf16.bf16.f32 "
        "{%0,%1,%2,%3}, {%4,%5,%6,%7}, {%8,%9}, {%0,%1,%2,%3};"
        : "+f"(d[0]), "+f"(d[1]), "+f"(d[2]), "+f"(d[3])
        : "r"(a[0]), "r"(a[1]), "r"(a[2]), "r"(a[3]), "r"(b[0]), "r"(b[1]));
}
__device__ __forceinline__ float ex2(float x) {
    float y;
    asm("ex2.approx.f32 %0, %1;" : "=f"(y) : "f"(x));
    return y;
}

// ---------------------------------------------------------------------------
// fp32 -> fp16 hi/lo split (activations)
// ---------------------------------------------------------------------------
__global__ void split_h_kernel(const float* __restrict__ x,
                               __half* __restrict__ hi,
                               __half* __restrict__ lo, int n4)
{
    int i = blockIdx.x * blockDim.x + threadIdx.x;
    if (i >= n4) return;
    float4 v = ((const float4*)x)[i];
    __half h0 = __float2half_rn(v.x);
    __half h1 = __float2half_rn(v.y);
    __half h2 = __float2half_rn(v.z);
    __half h3 = __float2half_rn(v.w);
    __half l0 = __float2half_rn(v.x - __half2float(h0));
    __half l1 = __float2half_rn(v.y - __half2float(h1));
    __half l2 = __float2half_rn(v.z - __half2float(h2));
    __half l3 = __float2half_rn(v.w - __half2float(h3));
    ((__half2*)hi)[2*i]   = __halves2half2(h0, h1);
    ((__half2*)hi)[2*i+1] = __halves2half2(h2, h3);
    ((__half2*)lo)[2*i]   = __halves2half2(l0, l1);
    ((__half2*)lo)[2*i+1] = __halves2half2(l2, l3);
}

// fp32 -> fp16 single rounding (weights)
__global__ void round_h_kernel(const float* __restrict__ x,
                               __half* __restrict__ h, int n4)
{
    int i = blockIdx.x * blockDim.x + threadIdx.x;
    if (i >= n4) return;
    float4 v = ((const float4*)x)[i];
    ((__half2*)h)[2*i]   = __floats2half2_rn(v.x, v.y);
    ((__half2*)h)[2*i+1] = __floats2half2_rn(v.z, v.w);
}

// ---------------------------------------------------------------------------
// V transpose + split (bf16 for attention)
// ---------------------------------------------------------------------------
__global__ void vtsplit_kernel(const float* __restrict__ V,
                               __nv_bfloat16* __restrict__ vh,
                               __nv_bfloat16* __restrict__ vl)
{
    __shared__ float t[32][33];
    const int k0 = blockIdx.x * 32, d0 = blockIdx.y * 32, f = blockIdx.z;
    const int tx = threadIdx.x & 31, ty = threadIdx.x >> 5;
    #pragma unroll
    for (int i = 0; i < 4; i++) {
        int key = k0 + ty + i * 8;
        t[ty + i * 8][tx] = V[(size_t)(f * NQ_ + key) * D_ + d0 + tx];
    }
    __syncthreads();
    #pragma unroll
    for (int i = 0; i < 4; i++) {
        int dd = ty + i * 8;
        int d = d0 + dd, h = d >> 6, dl = d & 63;
        float v = t[tx][dd];
        __nv_bfloat16 hi = __float2bfloat16(v);
        __nv_bfloat16 lo = __float2bfloat16(v - __bfloat162float(hi));
        size_t oi = ((size_t)(f * 16 + h) * 64 + dl) * NK_ + k0 + tx;
        vh[oi] = hi;
        vl[oi] = lo;
    }
}

// ---------------------------------------------------------------------------
// Fused bias precompute (head-independent)
// ---------------------------------------------------------------------------
__global__ void bias_kernel(const float* __restrict__ cq, const float* __restrict__ ck,
                            const float* __restrict__ qm, const float* __restrict__ km,
                            float* __restrict__ E)
{
    const int q = blockIdx.x, f = blockIdx.y, k = threadIdx.x;
    const int qi = f * NQ_ + q, ki = f * NK_ + k;
    float qy = cq[qi * 3 + 1], qx = cq[qi * 3 + 2];
    float dy = qy - ck[ki * 3 + 1];
    float dx = qx - ck[ki * 3 + 2];
    float dist = sqrtf(dy * dy + dx * dx);
    bool bad = (qm[qi] + km[ki] > 0.f) || (dist > 0.5f);
    E[(size_t)qi * NK_ + k] = bad ? -3.0e38f : __expf(-10.f * dist);
}

// ---------------------------------------------------------------------------
// HMMA GEMM, fp16 2-term split: C = (Ahi+Alo) @ Bh^T + bias.
// 128x128 CTA tile, 4 warps (64x64), 32 k-chunks; per chunk the B-tile
// fragments are register-held and reused for the Ahi and Alo MMA groups.
// 3-stage cp.async pipeline, one __syncthreads per chunk.
// ---------------------------------------------------------------------------
#define TILE_B 10240            // 128 rows * 80 B
#define STAGE  (3 * TILE_B)     // Ahi + Alo + B tiles per stage
#define NCH    32

__global__ void __launch_bounds__(128, 2)
gemm_mma(const __half* __restrict__ Ah, const __half* __restrict__ Al,
         const __half* __restrict__ Bh,
         const float* __restrict__ bias, float* __restrict__ C)
{
    extern __shared__ char dsm[];
    const uint32_t sbase = smem_u32(dsm);

    const int tid  = threadIdx.x;
    const int wid  = tid >> 5;
    const int lane = tid & 31;
    const int m0 = blockIdx.y * 128;
    const int n0 = blockIdx.x * 128;
    const int wm = (wid & 1) * 64;
    const int wn = (wid >> 1) * 64;

    float acc[4][8][4];
    #pragma unroll
    for (int mt = 0; mt < 4; mt++)
        #pragma unroll
        for (int nt = 0; nt < 8; nt++)
            #pragma unroll
            for (int r = 0; r < 4; r++) acc[mt][nt][r] = 0.f;

    // per-thread load slots: 1536 cp16 per chunk (3 tiles), 12 per thread
    int l_tl[12], l_row[12], l_c[12];
    #pragma unroll
    for (int j = 0; j < 12; j++) {
        int i = tid + j * 128;
        l_tl[j]  = i >> 9;             // 0=Ahi, 1=Alo, 2=B
        l_row[j] = (i & 511) >> 2;
        l_c[j]   = i & 3;
    }

    auto issue_load = [&](int ch, int buf) {
        const int k0 = ch * 32;
        #pragma unroll
        for (int j = 0; j < 12; j++) {
            const __half* g;
            if (l_tl[j] == 2)      g = Bh + (size_t)(n0 + l_row[j]) * GK + k0 + l_c[j] * 8;
            else if (l_tl[j] == 1) g = Al + (size_t)(m0 + l_row[j]) * GK + k0 + l_c[j] * 8;
            else                   g = Ah + (size_t)(m0 + l_row[j]) * GK + k0 + l_c[j] * 8;
            uint32_t s = sbase + buf * STAGE + l_tl[j] * TILE_B
                       + l_row[j] * 80 + l_c[j] * 16;
            cp16(s, g);
        }
        cp_commit();
    };

    issue_load(0, 0);
    issue_load(1, 1);

    for (int ch = 0; ch < NCH; ch++) {
        if (ch == NCH - 1) cp_wait0(); else cp_wait1();
        __syncthreads();
        if (ch + 2 < NCH) issue_load(ch + 2, (ch + 2) % 3);

        const uint32_t hbase = sbase + (ch % 3) * STAGE;
        const uint32_t lbase = hbase + TILE_B;
        const uint32_t bbase = hbase + 2 * TILE_B;

        #pragma unroll
        for (int ks = 0; ks < 2; ks++) {
            uint32_t b[8][2];
            #pragma unroll
            for (int np = 0; np < 4; np++) {
                uint32_t addr = bbase
                    + (wn + np * 16 + (lane & 7) + ((lane >> 4) & 1) * 8) * 80
                    + ((lane >> 3) & 1) * 16 + ks * 32;
                uint32_t r[4];
                ldm_x4(r, addr);
                b[np * 2][0] = r[0];     b[np * 2][1] = r[1];
                b[np * 2 + 1][0] = r[2]; b[np * 2 + 1][1] = r[3];
            }
            uint32_t a[4][4];
            #pragma unroll
            for (int mt = 0; mt < 4; mt++) {
                uint32_t addr = hbase + (wm + mt * 16 + (lane & 15)) * 80
                              + (lane >> 4) * 16 + ks * 32;
                ldm_x4(a[mt], addr);
            }
            #pragma unroll
            for (int mt = 0; mt < 4; mt++)
                #pragma unroll
                for (int nt = 0; nt < 8; nt++)
                    mma_f16(acc[mt][nt], a[mt], b[nt]);
            #pragma unroll
            for (int mt = 0; mt < 4; mt++) {
                uint32_t addr = lbase + (wm + mt * 16 + (lane & 15)) * 80
                              + (lane >> 4) * 16 + ks * 32;
                ldm_x4(a[mt], addr);
            }
            #pragma unroll
            for (int mt = 0; mt < 4; mt++)
                #pragma unroll
                for (int nt = 0; nt < 8; nt++)
                    mma_f16(acc[mt][nt], a[mt], b[nt]);
        }
    }

    // epilogue: +bias, write fp32
    const int cbase = n0 + wn + (lane & 3) * 2;
    float bv[8][2];
    #pragma unroll
    for (int nt = 0; nt < 8; nt++) {
        bv[nt][0] = bias[cbase + nt * 8];
        bv[nt][1] = bias[cbase + nt * 8 + 1];
    }
    #pragma unroll
    for (int mt = 0; mt < 4; mt++) {
        int r0 = m0 + wm + mt * 16 + (lane >> 2);
        #pragma unroll
        for (int nt = 0; nt < 8; nt++) {
            int c = cbase + nt * 8;
            float2 v0 = { acc[mt][nt][0] + bv[nt][0], acc[mt][nt][1] + bv[nt][1] };
            float2 v1 = { acc[mt][nt][2] + bv[nt][0], acc[mt][nt][3] + bv[nt][1] };
            *(float2*)&C[(size_t)r0 * GN + c]       = v0;
            *(float2*)&C[(size_t)(r0 + 8) * GN + c] = v1;
        }
    }
}

// ---------------------------------------------------------------------------
// Mask dtype detection + expansion
// ---------------------------------------------------------------------------
__global__ void detect_mask_kernel(const unsigned* __restrict__ qm,
                                   const unsigned* __restrict__ km, int nints)
{
    __shared__ int s_i, s_f;
    for (int b = 0; b < 2; b++) {
        if (threadIdx.x == 0) { s_i = 1; s_f = 1; }
        __syncthreads();
        const unsigned* p = b ? km : qm;
        int li = 1, lf = 1;
        for (int i = threadIdx.x; i < nints; i += blockDim.x) {
            unsigned v = p[i];
            if (v > 1u) li = 0;
            if (v != 0u && v != 0x3f800000u) lf = 0;
        }
        if (!li) atomicAnd(&s_i, 0);
        if (!lf) atomicAnd(&s_f, 0);
        __syncthreads();
        if (threadIdx.x == 0)
            g_mask_mode[b] = s_i ? 1 : (s_f ? 2 : 0);
        __syncthreads();
    }
}

__global__ void expand_mask_kernel(const void* __restrict__ src,
                                   float* __restrict__ dst, int n, int which)
{
    int mode = g_mask_mode[which];
    int i = blockIdx.x * blockDim.x + threadIdx.x;
    if (i >= n) return;
    bool m;
    if (mode == 1)      m = ((const int*)src)[i] != 0;
    else if (mode == 2) m = ((const float*)src)[i] != 0.f;
    else                m = ((const unsigned char*)src)[i] != 0;
    dst[i] = m ? 1.f : 0.f;
}

// ---------------------------------------------------------------------------
// 4D RoPE fused with bf16 hi/lo split (attention operands)
// ---------------------------------------------------------------------------
__global__ void rope_split_kernel(const float* __restrict__ X,
                                  const float* __restrict__ coords,
                                  const float* __restrict__ f0,
                                  const float* __restrict__ f1,
                                  const float* __restrict__ f2,
                                  __nv_bfloat16* __restrict__ hi,
                                  __nv_bfloat16* __restrict__ lo)
{
    __shared__ float cs[32], sn[32];
    const int tok = blockIdx.x;
    const int tid = threadIdx.x;

    if (tid < 32) {
        float coord, fr;
        if (tid < 12)      { coord = coords[tok * 3 + 0]; fr = f0[tid]; }
        else if (tid < 22) { coord = coords[tok * 3 + 1]; fr = f1[tid - 12]; }
        else               { coord = coords[tok * 3 + 2]; fr = f2[tid - 22]; }
        float arg = 1.5707963267948966f * coord * fr;
        float s, c;
        sincosf(arg, &s, &c);
        sn[tid] = s; cs[tid] = c;
    }
    __syncthreads();

    const float* xp = X + (size_t)tok * D_;
    __nv_bfloat162* hp = (__nv_bfloat162*)(hi + (size_t)tok * D_);
    __nv_bfloat162* lp = (__nv_bfloat162*)(lo + (size_t)tok * D_);
    for (int p = tid; p < H_ * 32; p += blockDim.x) {
        int h = p >> 5, j = p & 31;
        int idx = h * 64 + j * 2;
        float x0 = xp[idx], x1 = xp[idx + 1];
        float c = cs[j], s = sn[j];
        float y0 = x0 * c - x1 * s;
        float y1 = x1 * c + x0 * s;
        __nv_bfloat162 hv = __float22bfloat162_rn(make_float2(y0, y1));
        __nv_bfloat162 lv = __float22bfloat162_rn(make_float2(
            y0 - __bfloat162float(hv.x), y1 - __bfloat162float(hv.y)));
        hp[idx >> 1] = hv;
        lp[idx >> 1] = lv;
    }
}

// ---------------------------------------------------------------------------
// HMMA flash attention (bf16 3-pass); epilogue writes fp16 hi/lo for Wo GEMM.
// ---------------------------------------------------------------------------
#define ATT_SMEM 54272

__global__ void __launch_bounds__(128)
attn_mma(const __nv_bfloat16* __restrict__ Qh, const __nv_bfloat16* __restrict__ Ql,
         const __nv_bfloat16* __restrict__ Kh, const __nv_bfloat16* __restrict__ Kl,
         const __nv_bfloat16* __restrict__ Vth, const __nv_bfloat16* __restrict__ Vtl,
         const float* __restrict__ E, const float* __restrict__ alpha,
         __half* __restrict__ Yh, __half* __restrict__ Yl)
{
    extern __shared__ char sm[];
    uint32_t* sKh = (uint32_t*)sm;
    uint32_t* sKl = (uint32_t*)(sm + 9216);
    uint32_t* sVh = (uint32_t*)(sm + 18432);
    uint32_t* sVl = (uint32_t*)(sm + 27648);
    float*    sE  = (float*)(sm + 36864);

    const int tid = threadIdx.x;
    const int w = tid >> 5, lane = tid & 31;
    const int c = lane & 3, rg = lane >> 2;
    const int qb = blockIdx.x, fh = blockIdx.y;
    const int f = fh >> 4, h = fh & 15;
    const int tok0 = f * NQ_;
    const int q0 = qb * 64;
    const float alph = alpha[h];
    const int rl = 16 * w + rg;

    for (int i = tid; i < 512; i += 128) {
        int row = i >> 3, c16 = i & 7;
        size_t go = (size_t)(tok0 + q0 + row) * D_ + h * 64 + c16 * 8;
        *(uint4*)(sKh + row * 36 + c16 * 4) = *(const uint4*)(Qh + go);
        *(uint4*)(sKl + row * 36 + c16 * 4) = *(const uint4*)(Ql + go);
    }
    __syncthreads();
    uint32_t qhF[4][4], qlF[4][4];
    #pragma unroll
    for (int s = 0; s < 4; s++) {
        qhF[s][0] = sKh[rl * 36 + 8 * s + c];
        qhF[s][1] = sKh[(rl + 8) * 36 + 8 * s + c];
        qhF[s][2] = sKh[rl * 36 + 8 * s + c + 4];
        qhF[s][3] = sKh[(rl + 8) * 36 + 8 * s + c + 4];
        qlF[s][0] = sKl[rl * 36 + 8 * s + c];
        qlF[s][1] = sKl[(rl + 8) * 36 + 8 * s + c];
        qlF[s][2] = sKl[rl * 36 + 8 * s + c + 4];
        qlF[s][3] = sKl[(rl + 8) * 36 + 8 * s + c + 4];
    }
    __syncthreads();

    float o[8][4];
    #pragma unroll
    for (int n = 0; n < 8; n++)
        #pragma unroll
        for (int r = 0; r < 4; r++) o[n][r] = 0.f;
    float m0r = -3.0e38f, m1r = -3.0e38f, l0r = 0.f, l1r = 0.f;

    for (int kt = 0; kt < 9; kt++) {
        const int k0 = kt * 64;
        for (int i = tid; i < 512; i += 128) {
            int row = i >> 3, c16 = i & 7;
            size_t go = (size_t)(tok0 + k0 + row) * D_ + h * 64 + c16 * 8;
            *(uint4*)(sKh + row * 36 + c16 * 4) = *(const uint4*)(Kh + go);
            *(uint4*)(sKl + row * 36 + c16 * 4) = *(const uint4*)(Kl + go);
            size_t vo = (size_t)fh * (64 * NK_) + (size_t)row * NK_ + k0 + c16 * 8;
            *(uint4*)(sVh + row * 36 + c16 * 4) = *(const uint4*)(Vth + vo);
            *(uint4*)(sVl + row * 36 + c16 * 4) = *(const uint4*)(Vtl + vo);
        }
        for (int i = tid; i < 1024; i += 128) {
            int row = i >> 4, c4 = i & 15;
            *(float4*)(sE + row * 68 + c4 * 4) =
                *(const float4*)(E + (size_t)(tok0 + q0 + row) * NK_ + k0 + c4 * 4);
        }
        __syncthreads();

        float s[8][4];
        #pragma unroll
        for (int n = 0; n < 8; n++)
            #pragma unroll
            for (int r = 0; r < 4; r++) s[n][r] = 0.f;
        #pragma unroll
        for (int st = 0; st < 4; st++) {
            #pragma unroll
            for (int n = 0; n < 8; n++) {
                int bi = (8 * n + rg) * 36 + 8 * st + c;
                uint32_t bh[2] = { sKh[bi], sKh[bi + 4] };
                uint32_t bl[2] = { sKl[bi], sKl[bi + 4] };
                mma_bf16(s[n], qhF[st], bh);
                mma_bf16(s[n], qlF[st], bh);
                mma_bf16(s[n], qhF[st], bl);
            }
        }

        float mn0 = m0r, mn1 = m1r;
        #pragma unroll
        for (int n = 0; n < 8; n++) {
            float2 e0 = *(float2*)(sE + rl * 68 + 8 * n + 2 * c);
            float2 e1 = *(float2*)(sE + (rl + 8) * 68 + 8 * n + 2 * c);
            s[n][0] = (e0.x < 0.f) ? NEGBIG : fmaf(s[n][0], 0.125f, alph * e0.x);
            s[n][1] = (e0.y < 0.f) ? NEGBIG : fmaf(s[n][1], 0.125f, alph * e0.y);
            s[n][2] = (e1.x < 0.f) ? NEGBIG : fmaf(s[n][2], 0.125f, alph * e1.x);
            s[n][3] = (e1.y < 0.f) ? NEGBIG : fmaf(s[n][3], 0.125f, alph * e1.y);
            mn0 = fmaxf(mn0, fmaxf(s[n][0], s[n][1]));
            mn1 = fmaxf(mn1, fmaxf(s[n][2], s[n][3]));
        }
        mn0 = fmaxf(mn0, __shfl_xor_sync(0xffffffffu, mn0, 1));
        mn0 = fmaxf(mn0, __shfl_xor_sync(0xffffffffu, mn0, 2));
        mn1 = fmaxf(mn1, __shfl_xor_sync(0xffffffffu, mn1, 1));
        mn1 = fmaxf(mn1, __shfl_xor_sync(0xffffffffu, mn1, 2));
        float f0 = ex2((m0r - mn0) * LOG2E);
        float f1 = ex2((m1r - mn1) * LOG2E);
        m0r = mn0; m1r = mn1;

        float rs0 = 0.f, rs1 = 0.f;
        uint32_t phL[8], phH[8], plL[8], plH[8];
        #pragma unroll
        for (int n = 0; n < 8; n++) {
            float p0 = ex2((s[n][0] - mn0) * LOG2E);
            float p1 = ex2((s[n][1] - mn0) * LOG2E);
            float p2 = ex2((s[n][2] - mn1) * LOG2E);
            float p3 = ex2((s[n][3] - mn1) * LOG2E);
            rs0 += p0 + p1;
            rs1 += p2 + p3;
            o[n][0] *= f0; o[n][1] *= f0; o[n][2] *= f1; o[n][3] *= f1;
            __nv_bfloat162 bL = __float22bfloat162_rn(make_float2(p0, p1));
            phL[n] = *(uint32_t*)&bL;
            __nv_bfloat162 rL = __float22bfloat162_rn(make_float2(
                p0 - __bfloat162float(bL.x), p1 - __bfloat162float(bL.y)));
            plL[n] = *(uint32_t*)&rL;
            __nv_bfloat162 bH = __float22bfloat162_rn(make_float2(p2, p3));
            phH[n] = *(uint32_t*)&bH;
            __nv_bfloat162 rH = __float22bfloat162_rn(make_float2(
                p2 - __bfloat162float(bH.x), p3 - __bfloat162float(bH.y)));
            plH[n] = *(uint32_t*)&rH;
        }
        rs0 += __shfl_xor_sync(0xffffffffu, rs0, 1);
        rs0 += __shfl_xor_sync(0xffffffffu, rs0, 2);
        rs1 += __shfl_xor_sync(0xffffffffu, rs1, 1);
        rs1 += __shfl_xor_sync(0xffffffffu, rs1, 2);
        l0r = l0r * f0 + rs0;
        l1r = l1r * f1 + rs1;

        #pragma unroll
        for (int st = 0; st < 4; st++) {
            uint32_t ah[4] = { phL[2 * st], phH[2 * st], phL[2 * st + 1], phH[2 * st + 1] };
            uint32_t al[4] = { plL[2 * st], plH[2 * st], plL[2 * st + 1], plH[2 * st + 1] };
            #pragma unroll
            for (int n = 0; n < 8; n++) {
                int bi = (8 * n + rg) * 36 + 8 * st + c;
                uint32_t vh[2] = { sVh[bi], sVh[bi + 4] };
                uint32_t vl[2] = { sVl[bi], sVl[bi + 4] };
                mma_bf16(o[n], ah, vh);
                mma_bf16(o[n], al, vh);
                mma_bf16(o[n], ah, vl);
            }
        }
        __syncthreads();
    }

    // epilogue: write fp16 hi/lo directly (feeds Wo GEMM)
    float i0 = 1.f / l0r, i1 = 1.f / l1r;
    #pragma unroll
    for (int n = 0; n < 8; n++) {
        size_t e0 = ((size_t)(tok0 + q0 + rl) * D_ + h * 64 + 8 * n + 2 * c) >> 1;
        size_t e1 = ((size_t)(tok0 + q0 + rl + 8) * D_ + h * 64 + 8 * n + 2 * c) >> 1;
        float2 w0 = { o[n][0] * i0, o[n][1] * i0 };
        float2 w1 = { o[n][2] * i1, o[n][3] * i1 };
        __half2 h0 = __floats2half2_rn(w0.x, w0.y);
        __half2 l0v = __floats2half2_rn(w0.x - __half2float(__low2half(h0)),
                                        w0.y - __half2float(__high2half(h0)));
        __half2 h1 = __floats2half2_rn(w1.x, w1.y);
        __half2 l1v = __floats2half2_rn(w1.x - __half2float(__low2half(h1)),
                                        w1.y - __half2float(__high2half(h1)));
        ((__half2*)Yh)[e0] = h0;
        ((__half2*)Yl)[e0] = l0v;
        ((__half2*)Yh)[e1] = h1;
        ((__half2*)Yl)[e1] = l1v;
    }
}

// ---------------------------------------------------------------------------
extern "C" void kernel_launch(void* const* d_in, const int* in_sizes, int n_in,
                              void* d_out, int out_size)
{
    (void)in_sizes; (void)n_in; (void)out_size;

    const float*   q_tokens  = (const float*)d_in[0];
    const float*   kv_tokens = (const float*)d_in[1];
    const float*   coords_q  = (const float*)d_in[2];
    const float*   coords_k  = (const float*)d_in[3];
    const void*    q_pad     = d_in[4];
    const void*    kv_pad    = d_in[5];
    const float*   Wq = (const float*)d_in[6];
    const float*   bq = (const float*)d_in[7];
    const float*   Wk = (const float*)d_in[8];
    const float*   bk = (const float*)d_in[9];
    const float*   Wv = (const float*)d_in[10];
    const float*   bv = (const float*)d_in[11];
    const float*   Wo = (const float*)d_in[12];
    const float*   bo = (const float*)d_in[13];
    const float*   alpha = (const float*)d_in[14];
    const float*   f0 = (const float*)d_in[15];
    const float*   f1 = (const float*)d_in[16];
    const float*   f2 = (const float*)d_in[17];
    float* out = (float*)d_out;

    float *Qb, *Kb, *Vb, *qmB, *kmB, *Eb;
    cudaGetSymbolAddress((void**)&Qb, g_Q);
    cudaGetSymbolAddress((void**)&Kb, g_K);
    cudaGetSymbolAddress((void**)&Vb, g_V);
    cudaGetSymbolAddress((void**)&qmB, g_qm);
    cudaGetSymbolAddress((void**)&kmB, g_km);
    cudaGetSymbolAddress((void**)&Eb, g_E);

    __half *qhi, *qlo, *kvhi, *kvlo, *yhi, *ylo, *Wqh, *Wkh, *Wvh, *Woh;
    __nv_bfloat16 *aQh, *aQl, *aKh, *aKl, *vth, *vtl;
    cudaGetSymbolAddress((void**)&qhi,  g_qhi);  cudaGetSymbolAddress((void**)&qlo,  g_qlo);
    cudaGetSymbolAddress((void**)&kvhi, g_kvhi); cudaGetSymbolAddress((void**)&kvlo, g_kvlo);
    cudaGetSymbolAddress((void**)&yhi,  g_yhi);  cudaGetSymbolAddress((void**)&ylo,  g_ylo);
    cudaGetSymbolAddress((void**)&Wqh, g_Wqh);   cudaGetSymbolAddress((void**)&Wkh, g_Wkh);
    cudaGetSymbolAddress((void**)&Wvh, g_Wvh);   cudaGetSymbolAddress((void**)&Woh, g_Woh);
    cudaGetSymbolAddress((void**)&aQh, g_aQh);   cudaGetSymbolAddress((void**)&aQl, g_aQl);
    cudaGetSymbolAddress((void**)&aKh, g_aKh);   cudaGetSymbolAddress((void**)&aKl, g_aKl);
    cudaGetSymbolAddress((void**)&vth, g_vth);   cudaGetSymbolAddress((void**)&vtl, g_vtl);

    const int gemm_smem = 3 * STAGE;  // 92160
    cudaFuncSetAttribute(gemm_mma, cudaFuncAttributeMaxDynamicSharedMemorySize,
                         gemm_smem);
    cudaFuncSetAttribute(attn_mma, cudaFuncAttributeMaxDynamicSharedMemorySize,
                         ATT_SMEM);

    // masks + fused bias
    detect_mask_kernel<<<1, 256>>>((const unsigned*)q_pad, (const unsigned*)kv_pad,
                                   TOK / 4);
    expand_mask_kernel<<<(TOK + 255) / 256, 256>>>(q_pad,  qmB, TOK, 0);
    expand_mask_kernel<<<(TOK + 255) / 256, 256>>>(kv_pad, kmB, TOK, 1);
    bias_kernel<<<dim3(NQ_, 8), NK_>>>(coords_q, coords_k, qmB, kmB, Eb);

    // fp16 splits: activations hi/lo, weights single-rounded
    const int ntok4 = TOK * D_ / 4, nw4 = D_ * D_ / 4;
    split_h_kernel<<<(ntok4 + 255) / 256, 256>>>(q_tokens,  qhi,  qlo,  ntok4);
    split_h_kernel<<<(ntok4 + 255) / 256, 256>>>(kv_tokens, kvhi, kvlo, ntok4);
    round_h_kernel<<<(nw4 + 255) / 256, 256>>>(Wq, Wqh, nw4);
    round_h_kernel<<<(nw4 + 255) / 256, 256>>>(Wk, Wkh, nw4);
    round_h_kernel<<<(nw4 + 255) / 256, 256>>>(Wv, Wvh, nw4);
    round_h_kernel<<<(nw4 + 255) / 256, 256>>>(Wo, Woh, nw4);

    dim3 gg(GN / 128, TOK / 128);
    gemm_mma<<<gg, 128, gemm_smem>>>(qhi,  qlo,  Wqh, bq, Qb);
    gemm_mma<<<gg, 128, gemm_smem>>>(kvhi, kvlo, Wkh, bk, Kb);
    gemm_mma<<<gg, 128, gemm_smem>>>(kvhi, kvlo, Wvh, bv, Vb);

    // RoPE fused with attention-operand split (bf16)
    rope_split_kernel<<<TOK, 128>>>(Qb, coords_q, f0, f1, f2, aQh, aQl);
    rope_split_kernel<<<TOK, 128>>>(Kb, coords_k, f0, f1, f2, aKh, aKl);
    vtsplit_kernel<<<dim3(NK_ / 32, D_ / 32, 8), 256>>>(Vb, vth, vtl);

    attn_mma<<<dim3(9, 128), 128, ATT_SMEM>>>(aQh, aQl, aKh, aKl, vth, vtl,
                                              Eb, alpha, yhi, ylo);

    gemm_mma<<<gg, 128, gemm_smem>>>(yhi, ylo, Woh, bo, out);
}

// round 8
// speedup vs baseline: 2.9130x; 1.0443x over previous
#include <cuda_runtime.h>
#include <cuda_bf16.h>
#include <cuda_fp16.h>
#include <cstdint>
#include <cstddef>
#include <math.h>

// Problem constants
#define B_   2
#define T_   4
#define NQ_  576
#define NK_  576
#define D_   1024
#define H_   16
#define DH_  64
#define TOK  (B_*T_*NQ_)
#define NEGBIG (-1.7014118e38f)
#define LOG2E 1.4426950408889634f

#define GK 1024
#define GN 1024

// Scratch (device globals; no dynamic allocation allowed)
__device__ float g_Q[TOK * D_];
__device__ float g_K[TOK * D_];
__device__ float g_V[TOK * D_];
__device__ float g_qm[TOK];
__device__ float g_km[TOK];
__device__ int   g_mask_mode[2];
__device__ __nv_bfloat16 g_E[8 * NQ_ * NK_];

// fp16 hi/lo activations + single-rounded fp16 weights (GEMM path)
__device__ __half g_qhi[TOK * D_],  g_qlo[TOK * D_];
__device__ __half g_kvhi[TOK * D_], g_kvlo[TOK * D_];
__device__ __half g_yhi[TOK * D_],  g_ylo[TOK * D_];
__device__ __half g_Wqh[D_ * D_], g_Wkh[D_ * D_], g_Wvh[D_ * D_], g_Woh[D_ * D_];

// attention operands (fp16, post-rope): Q hi/lo, K single, V^T single
__device__ __half g_aQh[TOK * D_], g_aQl[TOK * D_];
__device__ __half g_aKr[TOK * D_];
__device__ __half g_vtr[128 * 64 * NK_];

// ---------------------------------------------------------------------------
// Family-portable PTX helpers
// ---------------------------------------------------------------------------
__device__ __forceinline__ uint32_t smem_u32(const void* p) {
    uint32_t a;
    asm("{ .reg .u64 t; cvta.to.shared.u64 t, %1; cvt.u32.u64 %0, t; }"
        : "=r"(a) : "l"(p));
    return a;
}
__device__ __forceinline__ void cp16(uint32_t s, const void* g) {
    asm volatile("cp.async.cg.shared.global [%0], [%1], 16;"
                 :: "r"(s), "l"(g) : "memory");
}
__device__ __forceinline__ void cp_commit() {
    asm volatile("cp.async.commit_group;" ::: "memory");
}
__device__ __forceinline__ void cp_wait1() {
    asm volatile("cp.async.wait_group 1;" ::: "memory");
}
__device__ __forceinline__ void cp_wait0() {
    asm volatile("cp.async.wait_group 0;" ::: "memory");
}
__device__ __forceinline__ void ldm_x4(uint32_t* r, uint32_t addr) {
    asm volatile("ldmatrix.sync.aligned.m8n8.x4.shared.b16 {%0,%1,%2,%3}, [%4];"
                 : "=r"(r[0]), "=r"(r[1]), "=r"(r[2]), "=r"(r[3]) : "r"(addr));
}
__device__ __forceinline__ void mma_f16(float* d, const uint32_t* a, const uint32_t* b) {
    asm volatile(
        "mma.sync.aligned.m16n8k16.row.col.f32.f16.f16.f32 "
        "{%0,%1,%2,%3}, {%4,%5,%6,%7}, {%8,%9}, {%0,%1,%2,%3};"
        : "+f"(d[0]), "+f"(d[1]), "+f"(d[2]), "+f"(d[3])
        : "r"(a[0]), "r"(a[1]), "r"(a[2]), "r"(a[3]), "r"(b[0]), "r"(b[1]));
}
__device__ __forceinline__ float ex2(float x) {
    float y;
    asm("ex2.approx.f32 %0, %1;" : "=f"(y) : "f"(x));
    return y;
}

// ---------------------------------------------------------------------------
// fp32 -> fp16 hi/lo split (activations)
// ---------------------------------------------------------------------------
__global__ void split_h_kernel(const float* __restrict__ x,
                               __half* __restrict__ hi,
                               __half* __restrict__ lo, int n4)
{
    int i = blockIdx.x * blockDim.x + threadIdx.x;
    if (i >= n4) return;
    float4 v = ((const float4*)x)[i];
    __half h0 = __float2half_rn(v.x);
    __half h1 = __float2half_rn(v.y);
    __half h2 = __float2half_rn(v.z);
    __half h3 = __float2half_rn(v.w);
    __half l0 = __float2half_rn(v.x - __half2float(h0));
    __half l1 = __float2half_rn(v.y - __half2float(h1));
    __half l2 = __float2half_rn(v.z - __half2float(h2));
    __half l3 = __float2half_rn(v.w - __half2float(h3));
    ((__half2*)hi)[2*i]   = __halves2half2(h0, h1);
    ((__half2*)hi)[2*i+1] = __halves2half2(h2, h3);
    ((__half2*)lo)[2*i]   = __halves2half2(l0, l1);
    ((__half2*)lo)[2*i+1] = __halves2half2(l2, l3);
}

// fp32 -> fp16 single rounding (weights)
__global__ void round_h_kernel(const float* __restrict__ x,
                               __half* __restrict__ h, int n4)
{
    int i = blockIdx.x * blockDim.x + threadIdx.x;
    if (i >= n4) return;
    float4 v = ((const float4*)x)[i];
    ((__half2*)h)[2*i]   = __floats2half2_rn(v.x, v.y);
    ((__half2*)h)[2*i+1] = __floats2half2_rn(v.z, v.w);
}

// ---------------------------------------------------------------------------
// V transpose + single fp16 round
// ---------------------------------------------------------------------------
__global__ void vtsplit_kernel(const float* __restrict__ V,
                               __half* __restrict__ vr)
{
    __shared__ float t[32][33];
    const int k0 = blockIdx.x * 32, d0 = blockIdx.y * 32, f = blockIdx.z;
    const int tx = threadIdx.x & 31, ty = threadIdx.x >> 5;
    #pragma unroll
    for (int i = 0; i < 4; i++) {
        int key = k0 + ty + i * 8;
        t[ty + i * 8][tx] = V[(size_t)(f * NQ_ + key) * D_ + d0 + tx];
    }
    __syncthreads();
    #pragma unroll
    for (int i = 0; i < 4; i++) {
        int dd = ty + i * 8;
        int d = d0 + dd, h = d >> 6, dl = d & 63;
        size_t oi = ((size_t)(f * 16 + h) * 64 + dl) * NK_ + k0 + tx;
        vr[oi] = __float2half_rn(t[tx][dd]);
    }
}

// ---------------------------------------------------------------------------
// Fused bias precompute (head-independent), bf16 output, smem k-coord reuse.
// block = 576 threads; each block: one frame x 8 q rows.
// ---------------------------------------------------------------------------
__global__ void __launch_bounds__(576)
bias_kernel(const float* __restrict__ cq, const float* __restrict__ ck,
            const float* __restrict__ qm, const float* __restrict__ km,
            __nv_bfloat16* __restrict__ E)
{
    __shared__ float ky[NK_], kx[NK_], kms[NK_];
    __shared__ float qy8[8], qx8[8], qm8[8];
    const int f = blockIdx.y, k = threadIdx.x;
    const int ki = f * NK_ + k;
    ky[k]  = ck[ki * 3 + 1];
    kx[k]  = ck[ki * 3 + 2];
    kms[k] = km[ki];
    if (threadIdx.x < 8) {
        int q = blockIdx.x * 8 + threadIdx.x;
        int qi = f * NQ_ + q;
        qy8[threadIdx.x] = cq[qi * 3 + 1];
        qx8[threadIdx.x] = cq[qi * 3 + 2];
        qm8[threadIdx.x] = qm[qi];
    }
    __syncthreads();
    #pragma unroll
    for (int r = 0; r < 8; r++) {
        int q = blockIdx.x * 8 + r;
        float dy = qy8[r] - ky[k];
        float dx = qx8[r] - kx[k];
        float dist = sqrtf(dy * dy + dx * dx);
        bool bad = (qm8[r] + kms[k] > 0.f) || (dist > 0.5f);
        E[(size_t)(f * NQ_ + q) * NK_ + k] =
            __float2bfloat16(bad ? -3.0e38f : __expf(-10.f * dist));
    }
}

// ---------------------------------------------------------------------------
// HMMA GEMM, fp16 2-term split (unchanged from round 7)
// ---------------------------------------------------------------------------
#define TILE_B 10240
#define STAGE  (3 * TILE_B)
#define NCH    32

__global__ void __launch_bounds__(128, 2)
gemm_mma(const __half* __restrict__ Ah, const __half* __restrict__ Al,
         const __half* __restrict__ Bh,
         const float* __restrict__ bias, float* __restrict__ C)
{
    extern __shared__ char dsm[];
    const uint32_t sbase = smem_u32(dsm);

    const int tid  = threadIdx.x;
    const int wid  = tid >> 5;
    const int lane = tid & 31;
    const int m0 = blockIdx.y * 128;
    const int n0 = blockIdx.x * 128;
    const int wm = (wid & 1) * 64;
    const int wn = (wid >> 1) * 64;

    float acc[4][8][4];
    #pragma unroll
    for (int mt = 0; mt < 4; mt++)
        #pragma unroll
        for (int nt = 0; nt < 8; nt++)
            #pragma unroll
            for (int r = 0; r < 4; r++) acc[mt][nt][r] = 0.f;

    int l_tl[12], l_row[12], l_c[12];
    #pragma unroll
    for (int j = 0; j < 12; j++) {
        int i = tid + j * 128;
        l_tl[j]  = i >> 9;
        l_row[j] = (i & 511) >> 2;
        l_c[j]   = i & 3;
    }

    auto issue_load = [&](int ch, int buf) {
        const int k0 = ch * 32;
        #pragma unroll
        for (int j = 0; j < 12; j++) {
            const __half* g;
            if (l_tl[j] == 2)      g = Bh + (size_t)(n0 + l_row[j]) * GK + k0 + l_c[j] * 8;
            else if (l_tl[j] == 1) g = Al + (size_t)(m0 + l_row[j]) * GK + k0 + l_c[j] * 8;
            else                   g = Ah + (size_t)(m0 + l_row[j]) * GK + k0 + l_c[j] * 8;
            uint32_t s = sbase + buf * STAGE + l_tl[j] * TILE_B
                       + l_row[j] * 80 + l_c[j] * 16;
            cp16(s, g);
        }
        cp_commit();
    };

    issue_load(0, 0);
    issue_load(1, 1);

    for (int ch = 0; ch < NCH; ch++) {
        if (ch == NCH - 1) cp_wait0(); else cp_wait1();
        __syncthreads();
        if (ch + 2 < NCH) issue_load(ch + 2, (ch + 2) % 3);

        const uint32_t hbase = sbase + (ch % 3) * STAGE;
        const uint32_t lbase = hbase + TILE_B;
        const uint32_t bbase = hbase + 2 * TILE_B;

        #pragma unroll
        for (int ks = 0; ks < 2; ks++) {
            uint32_t b[8][2];
            #pragma unroll
            for (int np = 0; np < 4; np++) {
                uint32_t addr = bbase
                    + (wn + np * 16 + (lane & 7) + ((lane >> 4) & 1) * 8) * 80
                    + ((lane >> 3) & 1) * 16 + ks * 32;
                uint32_t r[4];
                ldm_x4(r, addr);
                b[np * 2][0] = r[0];     b[np * 2][1] = r[1];
                b[np * 2 + 1][0] = r[2]; b[np * 2 + 1][1] = r[3];
            }
            uint32_t a[4][4];
            #pragma unroll
            for (int mt = 0; mt < 4; mt++) {
                uint32_t addr = hbase + (wm + mt * 16 + (lane & 15)) * 80
                              + (lane >> 4) * 16 + ks * 32;
                ldm_x4(a[mt], addr);
            }
            #pragma unroll
            for (int mt = 0; mt < 4; mt++)
                #pragma unroll
                for (int nt = 0; nt < 8; nt++)
                    mma_f16(acc[mt][nt], a[mt], b[nt]);
            #pragma unroll
            for (int mt = 0; mt < 4; mt++) {
                uint32_t addr = lbase + (wm + mt * 16 + (lane & 15)) * 80
                              + (lane >> 4) * 16 + ks * 32;
                ldm_x4(a[mt], addr);
            }
            #pragma unroll
            for (int mt = 0; mt < 4; mt++)
                #pragma unroll
                for (int nt = 0; nt < 8; nt++)
                    mma_f16(acc[mt][nt], a[mt], b[nt]);
        }
    }

    const int cbase = n0 + wn + (lane & 3) * 2;
    float bv[8][2];
    #pragma unroll
    for (int nt = 0; nt < 8; nt++) {
        bv[nt][0] = bias[cbase + nt * 8];
        bv[nt][1] = bias[cbase + nt * 8 + 1];
    }
    #pragma unroll
    for (int mt = 0; mt < 4; mt++) {
        int r0 = m0 + wm + mt * 16 + (lane >> 2);
        #pragma unroll
        for (int nt = 0; nt < 8; nt++) {
            int c = cbase + nt * 8;
            float2 v0 = { acc[mt][nt][0] + bv[nt][0], acc[mt][nt][1] + bv[nt][1] };
            float2 v1 = { acc[mt][nt][2] + bv[nt][0], acc[mt][nt][3] + bv[nt][1] };
            *(float2*)&C[(size_t)r0 * GN + c]       = v0;
            *(float2*)&C[(size_t)(r0 + 8) * GN + c] = v1;
        }
    }
}

// ---------------------------------------------------------------------------
// Mask dtype detection + expansion
// ---------------------------------------------------------------------------
__global__ void detect_mask_kernel(const unsigned* __restrict__ qm,
                                   const unsigned* __restrict__ km, int nints)
{
    __shared__ int s_i, s_f;
    for (int b = 0; b < 2; b++) {
        if (threadIdx.x == 0) { s_i = 1; s_f = 1; }
        __syncthreads();
        const unsigned* p = b ? km : qm;
        int li = 1, lf = 1;
        for (int i = threadIdx.x; i < nints; i += blockDim.x) {
            unsigned v = p[i];
            if (v > 1u) li = 0;
            if (v != 0u && v != 0x3f800000u) lf = 0;
        }
        if (!li) atomicAnd(&s_i, 0);
        if (!lf) atomicAnd(&s_f, 0);
        __syncthreads();
        if (threadIdx.x == 0)
            g_mask_mode[b] = s_i ? 1 : (s_f ? 2 : 0);
        __syncthreads();
    }
}

__global__ void expand_mask_kernel(const void* __restrict__ src,
                                   float* __restrict__ dst, int n, int which)
{
    int mode = g_mask_mode[which];
    int i = blockIdx.x * blockDim.x + threadIdx.x;
    if (i >= n) return;
    bool m;
    if (mode == 1)      m = ((const int*)src)[i] != 0;
    else if (mode == 2) m = ((const float*)src)[i] != 0.f;
    else                m = ((const unsigned char*)src)[i] != 0;
    dst[i] = m ? 1.f : 0.f;
}

// ---------------------------------------------------------------------------
// 4D RoPE fused with fp16 hi/lo split (Q operand)
// ---------------------------------------------------------------------------
__global__ void rope_split_q(const float* __restrict__ X,
                             const float* __restrict__ coords,
                             const float* __restrict__ f0,
                             const float* __restrict__ f1,
                             const float* __restrict__ f2,
                             __half* __restrict__ hi,
                             __half* __restrict__ lo)
{
    __shared__ float cs[32], sn[32];
    const int tok = blockIdx.x;
    const int tid = threadIdx.x;

    if (tid < 32) {
        float coord, fr;
        if (tid < 12)      { coord = coords[tok * 3 + 0]; fr = f0[tid]; }
        else if (tid < 22) { coord = coords[tok * 3 + 1]; fr = f1[tid - 12]; }
        else               { coord = coords[tok * 3 + 2]; fr = f2[tid - 22]; }
        float arg = 1.5707963267948966f * coord * fr;
        float s, c;
        sincosf(arg, &s, &c);
        sn[tid] = s; cs[tid] = c;
    }
    __syncthreads();

    const float* xp = X + (size_t)tok * D_;
    __half2* hp = (__half2*)(hi + (size_t)tok * D_);
    __half2* lp = (__half2*)(lo + (size_t)tok * D_);
    for (int p = tid; p < H_ * 32; p += blockDim.x) {
        int h = p >> 5, j = p & 31;
        int idx = h * 64 + j * 2;
        float x0 = xp[idx], x1 = xp[idx + 1];
        float c = cs[j], s = sn[j];
        float y0 = x0 * c - x1 * s;
        float y1 = x1 * c + x0 * s;
        __half2 hv = __floats2half2_rn(y0, y1);
        __half2 lv = __floats2half2_rn(y0 - __half2float(__low2half(hv)),
                                       y1 - __half2float(__high2half(hv)));
        hp[idx >> 1] = hv;
        lp[idx >> 1] = lv;
    }
}

// 4D RoPE with single fp16 rounding (K operand)
__global__ void rope_round_k(const float* __restrict__ X,
                             const float* __restrict__ coords,
                             const float* __restrict__ f0,
                             const float* __restrict__ f1,
                             const float* __restrict__ f2,
                             __half* __restrict__ out)
{
    __shared__ float cs[32], sn[32];
    const int tok = blockIdx.x;
    const int tid = threadIdx.x;

    if (tid < 32) {
        float coord, fr;
        if (tid < 12)      { coord = coords[tok * 3 + 0]; fr = f0[tid]; }
        else if (tid < 22) { coord = coords[tok * 3 + 1]; fr = f1[tid - 12]; }
        else               { coord = coords[tok * 3 + 2]; fr = f2[tid - 22]; }
        float arg = 1.5707963267948966f * coord * fr;
        float s, c;
        sincosf(arg, &s, &c);
        sn[tid] = s; cs[tid] = c;
    }
    __syncthreads();

    const float* xp = X + (size_t)tok * D_;
    __half2* op = (__half2*)(out + (size_t)tok * D_);
    for (int p = tid; p < H_ * 32; p += blockDim.x) {
        int h = p >> 5, j = p & 31;
        int idx = h * 64 + j * 2;
        float x0 = xp[idx], x1 = xp[idx + 1];
        float c = cs[j], s = sn[j];
        op[idx >> 1] = __floats2half2_rn(x0 * c - x1 * s, x1 * c + x0 * s);
    }
}

// ---------------------------------------------------------------------------
// HMMA flash attention, fp16 2-pass: S=(Qhi+Qlo)K^T, O=(Phi+Plo)V.
// smem: K tile (9216B), V^T tile (9216B), E bf16 tile (9216B) = 27648B.
// Q staged through K/V buffers before mainloop.
// ---------------------------------------------------------------------------
#define ATT_SMEM 27648

__global__ void __launch_bounds__(128)
attn_mma(const __half* __restrict__ Qh, const __half* __restrict__ Ql,
         const __half* __restrict__ Kr, const __half* __restrict__ Vtr,
         const __nv_bfloat16* __restrict__ E, const float* __restrict__ alpha,
         __half* __restrict__ Yh, __half* __restrict__ Yl)
{
    extern __shared__ char sm[];
    uint32_t* sK = (uint32_t*)sm;                       // 64 x 36 u32
    uint32_t* sV = (uint32_t*)(sm + 9216);              // 64 x 36 u32
    __nv_bfloat16* sE = (__nv_bfloat16*)(sm + 18432);   // 64 x 72 bf16

    const int tid = threadIdx.x;
    const int w = tid >> 5, lane = tid & 31;
    const int c = lane & 3, rg = lane >> 2;
    const int qb = blockIdx.x, fh = blockIdx.y;
    const int f = fh >> 4, h = fh & 15;
    const int tok0 = f * NQ_;
    const int q0 = qb * 64;
    const float alph = alpha[h];
    const int rl = 16 * w + rg;

    // stage Q hi (sK) / lo (sV), extract resident A fragments
    for (int i = tid; i < 512; i += 128) {
        int row = i >> 3, c16 = i & 7;
        size_t go = (size_t)(tok0 + q0 + row) * D_ + h * 64 + c16 * 8;
        *(uint4*)(sK + row * 36 + c16 * 4) = *(const uint4*)(Qh + go);
        *(uint4*)(sV + row * 36 + c16 * 4) = *(const uint4*)(Ql + go);
    }
    __syncthreads();
    uint32_t qhF[4][4], qlF[4][4];
    #pragma unroll
    for (int s = 0; s < 4; s++) {
        qhF[s][0] = sK[rl * 36 + 8 * s + c];
        qhF[s][1] = sK[(rl + 8) * 36 + 8 * s + c];
        qhF[s][2] = sK[rl * 36 + 8 * s + c + 4];
        qhF[s][3] = sK[(rl + 8) * 36 + 8 * s + c + 4];
        qlF[s][0] = sV[rl * 36 + 8 * s + c];
        qlF[s][1] = sV[(rl + 8) * 36 + 8 * s + c];
        qlF[s][2] = sV[rl * 36 + 8 * s + c + 4];
        qlF[s][3] = sV[(rl + 8) * 36 + 8 * s + c + 4];
    }
    __syncthreads();

    float o[8][4];
    #pragma unroll
    for (int n = 0; n < 8; n++)
        #pragma unroll
        for (int r = 0; r < 4; r++) o[n][r] = 0.f;
    float m0r = -3.0e38f, m1r = -3.0e38f, l0r = 0.f, l1r = 0.f;

    for (int kt = 0; kt < 9; kt++) {
        const int k0 = kt * 64;
        for (int i = tid; i < 512; i += 128) {
            int row = i >> 3, c16 = i & 7;
            size_t go = (size_t)(tok0 + k0 + row) * D_ + h * 64 + c16 * 8;
            *(uint4*)(sK + row * 36 + c16 * 4) = *(const uint4*)(Kr + go);
            size_t vo = (size_t)fh * (64 * NK_) + (size_t)row * NK_ + k0 + c16 * 8;
            *(uint4*)(sV + row * 36 + c16 * 4) = *(const uint4*)(Vtr + vo);
        }
        for (int i = tid; i < 512; i += 128) {
            int row = i >> 3, c8 = i & 7;
            *(uint4*)(sE + row * 72 + c8 * 8) =
                *(const uint4*)(E + (size_t)(tok0 + q0 + row) * NK_ + k0 + c8 * 8);
        }
        __syncthreads();

        // S = (Qhi + Qlo) K^T
        float s[8][4];
        #pragma unroll
        for (int n = 0; n < 8; n++)
            #pragma unroll
            for (int r = 0; r < 4; r++) s[n][r] = 0.f;
        #pragma unroll
        for (int st = 0; st < 4; st++) {
            #pragma unroll
            for (int n = 0; n < 8; n++) {
                int bi = (8 * n + rg) * 36 + 8 * st + c;
                uint32_t bh[2] = { sK[bi], sK[bi + 4] };
                mma_f16(s[n], qhF[st], bh);
                mma_f16(s[n], qlF[st], bh);
            }
        }

        // fused bias + online softmax
        float mn0 = m0r, mn1 = m1r;
        #pragma unroll
        for (int n = 0; n < 8; n++) {
            float2 e0 = __bfloat1622float2(
                *(__nv_bfloat162*)(sE + rl * 72 + 8 * n + 2 * c));
            float2 e1 = __bfloat1622float2(
                *(__nv_bfloat162*)(sE + (rl + 8) * 72 + 8 * n + 2 * c));
            s[n][0] = (e0.x < 0.f) ? NEGBIG : fmaf(s[n][0], 0.125f, alph * e0.x);
            s[n][1] = (e0.y < 0.f) ? NEGBIG : fmaf(s[n][1], 0.125f, alph * e0.y);
            s[n][2] = (e1.x < 0.f) ? NEGBIG : fmaf(s[n][2], 0.125f, alph * e1.x);
            s[n][3] = (e1.y < 0.f) ? NEGBIG : fmaf(s[n][3], 0.125f, alph * e1.y);
            mn0 = fmaxf(mn0, fmaxf(s[n][0], s[n][1]));
            mn1 = fmaxf(mn1, fmaxf(s[n][2], s[n][3]));
        }
        mn0 = fmaxf(mn0, __shfl_xor_sync(0xffffffffu, mn0, 1));
        mn0 = fmaxf(mn0, __shfl_xor_sync(0xffffffffu, mn0, 2));
        mn1 = fmaxf(mn1, __shfl_xor_sync(0xffffffffu, mn1, 1));
        mn1 = fmaxf(mn1, __shfl_xor_sync(0xffffffffu, mn1, 2));
        float f0 = ex2((m0r - mn0) * LOG2E);
        float f1 = ex2((m1r - mn1) * LOG2E);
        m0r = mn0; m1r = mn1;

        float rs0 = 0.f, rs1 = 0.f;
        uint32_t phL[8], phH[8], plL[8], plH[8];
        #pragma unroll
        for (int n = 0; n < 8; n++) {
            float p0 = ex2((s[n][0] - mn0) * LOG2E);
            float p1 = ex2((s[n][1] - mn0) * LOG2E);
            float p2 = ex2((s[n][2] - mn1) * LOG2E);
            float p3 = ex2((s[n][3] - mn1) * LOG2E);
            rs0 += p0 + p1;
            rs1 += p2 + p3;
            o[n][0] *= f0; o[n][1] *= f0; o[n][2] *= f1; o[n][3] *= f1;
            __half2 bL = __floats2half2_rn(p0, p1);
            phL[n] = *(uint32_t*)&bL;
            __half2 rL = __floats2half2_rn(p0 - __half2float(__low2half(bL)),
                                           p1 - __half2float(__high2half(bL)));
            plL[n] = *(uint32_t*)&rL;
            __half2 bH = __floats2half2_rn(p2, p3);
            phH[n] = *(uint32_t*)&bH;
            __half2 rH = __floats2half2_rn(p2 - __half2float(__low2half(bH)),
                                           p3 - __half2float(__high2half(bH)));
            plH[n] = *(uint32_t*)&rH;
        }
        rs0 += __shfl_xor_sync(0xffffffffu, rs0, 1);
        rs0 += __shfl_xor_sync(0xffffffffu, rs0, 2);
        rs1 += __shfl_xor_sync(0xffffffffu, rs1, 1);
        rs1 += __shfl_xor_sync(0xffffffffu, rs1, 2);
        l0r = l0r * f0 + rs0;
        l1r = l1r * f1 + rs1;

        // O += (Phi + Plo) V
        #pragma unroll
        for (int st = 0; st < 4; st++) {
            uint32_t ah[4] = { phL[2 * st], phH[2 * st], phL[2 * st + 1], phH[2 * st + 1] };
            uint32_t al[4] = { plL[2 * st], plH[2 * st], plL[2 * st + 1], plH[2 * st + 1] };
            #pragma unroll
            for (int n = 0; n < 8; n++) {
                int bi = (8 * n + rg) * 36 + 8 * st + c;
                uint32_t vh[2] = { sV[bi], sV[bi + 4] };
                mma_f16(o[n], ah, vh);
                mma_f16(o[n], al, vh);
            }
        }
        __syncthreads();
    }

    // epilogue: write fp16 hi/lo directly (feeds Wo GEMM)
    float i0 = 1.f / l0r, i1 = 1.f / l1r;
    #pragma unroll
    for (int n = 0; n < 8; n++) {
        size_t e0 = ((size_t)(tok0 + q0 + rl) * D_ + h * 64 + 8 * n + 2 * c) >> 1;
        size_t e1 = ((size_t)(tok0 + q0 + rl + 8) * D_ + h * 64 + 8 * n + 2 * c) >> 1;
        float2 w0 = { o[n][0] * i0, o[n][1] * i0 };
        float2 w1 = { o[n][2] * i1, o[n][3] * i1 };
        __half2 h0 = __floats2half2_rn(w0.x, w0.y);
        __half2 l0v = __floats2half2_rn(w0.x - __half2float(__low2half(h0)),
                                        w0.y - __half2float(__high2half(h0)));
        __half2 h1 = __floats2half2_rn(w1.x, w1.y);
        __half2 l1v = __floats2half2_rn(w1.x - __half2float(__low2half(h1)),
                                        w1.y - __half2float(__high2half(h1)));
        ((__half2*)Yh)[e0] = h0;
        ((__half2*)Yl)[e0] = l0v;
        ((__half2*)Yh)[e1] = h1;
        ((__half2*)Yl)[e1] = l1v;
    }
}

// ---------------------------------------------------------------------------
extern "C" void kernel_launch(void* const* d_in, const int* in_sizes, int n_in,
                              void* d_out, int out_size)
{
    (void)in_sizes; (void)n_in; (void)out_size;

    const float*   q_tokens  = (const float*)d_in[0];
    const float*   kv_tokens = (const float*)d_in[1];
    const float*   coords_q  = (const float*)d_in[2];
    const float*   coords_k  = (const float*)d_in[3];
    const void*    q_pad     = d_in[4];
    const void*    kv_pad    = d_in[5];
    const float*   Wq = (const float*)d_in[6];
    const float*   bq = (const float*)d_in[7];
    const float*   Wk = (const float*)d_in[8];
    const float*   bk = (const float*)d_in[9];
    const float*   Wv = (const float*)d_in[10];
    const float*   bv = (const float*)d_in[11];
    const float*   Wo = (const float*)d_in[12];
    const float*   bo = (const float*)d_in[13];
    const float*   alpha = (const float*)d_in[14];
    const float*   f0 = (const float*)d_in[15];
    const float*   f1 = (const float*)d_in[16];
    const float*   f2 = (const float*)d_in[17];
    float* out = (float*)d_out;

    float *Qb, *Kb, *Vb, *qmB, *kmB;
    __nv_bfloat16 *Eb;
    cudaGetSymbolAddress((void**)&Qb, g_Q);
    cudaGetSymbolAddress((void**)&Kb, g_K);
    cudaGetSymbolAddress((void**)&Vb, g_V);
    cudaGetSymbolAddress((void**)&qmB, g_qm);
    cudaGetSymbolAddress((void**)&kmB, g_km);
    cudaGetSymbolAddress((void**)&Eb, g_E);

    __half *qhi, *qlo, *kvhi, *kvlo, *yhi, *ylo, *Wqh, *Wkh, *Wvh, *Woh;
    __half *aQh, *aQl, *aKr, *vtr;
    cudaGetSymbolAddress((void**)&qhi,  g_qhi);  cudaGetSymbolAddress((void**)&qlo,  g_qlo);
    cudaGetSymbolAddress((void**)&kvhi, g_kvhi); cudaGetSymbolAddress((void**)&kvlo, g_kvlo);
    cudaGetSymbolAddress((void**)&yhi,  g_yhi);  cudaGetSymbolAddress((void**)&ylo,  g_ylo);
    cudaGetSymbolAddress((void**)&Wqh, g_Wqh);   cudaGetSymbolAddress((void**)&Wkh, g_Wkh);
    cudaGetSymbolAddress((void**)&Wvh, g_Wvh);   cudaGetSymbolAddress((void**)&Woh, g_Woh);
    cudaGetSymbolAddress((void**)&aQh, g_aQh);   cudaGetSymbolAddress((void**)&aQl, g_aQl);
    cudaGetSymbolAddress((void**)&aKr, g_aKr);   cudaGetSymbolAddress((void**)&vtr, g_vtr);

    const int gemm_smem = 3 * STAGE;  // 92160
    cudaFuncSetAttribute(gemm_mma, cudaFuncAttributeMaxDynamicSharedMemorySize,
                         gemm_smem);
    cudaFuncSetAttribute(attn_mma, cudaFuncAttributeMaxDynamicSharedMemorySize,
                         ATT_SMEM);

    // masks + fused bias
    detect_mask_kernel<<<1, 256>>>((const unsigned*)q_pad, (const unsigned*)kv_pad,
                                   TOK / 4);
    expand_mask_kernel<<<(TOK + 255) / 256, 256>>>(q_pad,  qmB, TOK, 0);
    expand_mask_kernel<<<(TOK + 255) / 256, 256>>>(kv_pad, kmB, TOK, 1);
    bias_kernel<<<dim3(NQ_ / 8, 8), NK_>>>(coords_q, coords_k, qmB, kmB, Eb);

    // fp16 splits: activations hi/lo, weights single-rounded
    const int ntok4 = TOK * D_ / 4, nw4 = D_ * D_ / 4;
    split_h_kernel<<<(ntok4 + 255) / 256, 256>>>(q_tokens,  qhi,  qlo,  ntok4);
    split_h_kernel<<<(ntok4 + 255) / 256, 256>>>(kv_tokens, kvhi, kvlo, ntok4);
    round_h_kernel<<<(nw4 + 255) / 256, 256>>>(Wq, Wqh, nw4);
    round_h_kernel<<<(nw4 + 255) / 256, 256>>>(Wk, Wkh, nw4);
    round_h_kernel<<<(nw4 + 255) / 256, 256>>>(Wv, Wvh, nw4);
    round_h_kernel<<<(nw4 + 255) / 256, 256>>>(Wo, Woh, nw4);

    dim3 gg(GN / 128, TOK / 128);
    gemm_mma<<<gg, 128, gemm_smem>>>(qhi,  qlo,  Wqh, bq, Qb);
    gemm_mma<<<gg, 128, gemm_smem>>>(kvhi, kvlo, Wkh, bk, Kb);
    gemm_mma<<<gg, 128, gemm_smem>>>(kvhi, kvlo, Wvh, bv, Vb);

    // RoPE: Q -> fp16 hi/lo, K -> fp16 single; V -> transposed fp16
    rope_split_q<<<TOK, 128>>>(Qb, coords_q, f0, f1, f2, aQh, aQl);
    rope_round_k<<<TOK, 128>>>(Kb, coords_k, f0, f1, f2, aKr);
    vtsplit_kernel<<<dim3(NK_ / 32, D_ / 32, 8), 256>>>(Vb, vtr);

    attn_mma<<<dim3(9, 128), 128, ATT_SMEM>>>(aQh, aQl, aKr, vtr,
                                              Eb, alpha, yhi, ylo);

    gemm_mma<<<gg, 128, gemm_smem>>>(yhi, ylo, Woh, bo, out);
}